// round 8
// baseline (speedup 1.0000x reference)
#include <cuda_runtime.h>
#include <cstdint>
#include <cfloat>
#include <cstddef>

#define BQ 2
#define NQ 8192
#define RQ 2048
#define KQ 16
#define COUTQ 128
#define GQ (BQ * RQ)

typedef unsigned long long u64;

// ---- packed fp32x2 helpers (sm_103a FFMA2; bit-exact IEEE fp32 per lane) ----
__device__ __forceinline__ u64 pk2(float lo, float hi) {
    u64 r;
    asm("mov.b64 %0, {%1, %2};" : "=l"(r)
        : "r"(__float_as_uint(lo)), "r"(__float_as_uint(hi)));
    return r;
}
__device__ __forceinline__ void fma2(u64& d, u64 a, u64 b) {
    asm("fma.rn.f32x2 %0, %1, %2, %0;" : "+l"(d) : "l"(a), "l"(b));
}
__device__ __forceinline__ float2 up2(u64 v) {
    unsigned lo, hi;
    asm("mov.b64 {%0, %1}, %2;" : "=r"(lo), "=r"(hi) : "l"(v));
    return make_float2(__uint_as_float(lo), __uint_as_float(hi));
}

// ---------------- scratch (no allocations allowed) ----------------
__device__ int    g_nn[BQ * RQ * KQ];          // neighbor indices per rep point
__device__ float  g_wt[1280 * COUTQ];          // conv_w transposed: Wt[j][o]
__device__ float  g_w1p[12 * 1024];            // t1_w packed: [jj][i][4k]
__device__ float  g_w2p[64 * 1024];            // t2_w packed: [jj][i][4k]
__device__ float  g_w3p[64 * 1024];            // t3_w packed: [jj][i][4k]
__device__ float4 g_pts4[BQ * NQ];             // (x, y, z, sq)
__device__ float  g_tf[(size_t)GQ * 1280];     // Tf flattened: A[g][j], j = c*16 + k
__device__ float  g_part[8][(size_t)GQ * COUTQ]; // split-K partials

// ---------------- kernel 1: prep (weight packing + point packing) ----------------
#define PREP_TOTAL 323584

__global__ void prep_kernel(const float* __restrict__ points,
                            const float* __restrict__ t1_w,
                            const float* __restrict__ t2_w,
                            const float* __restrict__ t3_w,
                            const float* __restrict__ conv_w) {
    int e = blockIdx.x * 256 + threadIdx.x;
    if (e < 163840) {
        int j = e >> 7, o = e & 127;
        g_wt[e] = __ldg(&conv_w[o * 1280 + j]);
    } else if (e < 180224) {
        int p = e - 163840;                       // b*NQ + n
        const float* pp = points + (size_t)p * 3;
        float x = __ldg(pp), y = __ldg(pp + 1), z = __ldg(pp + 2);
        g_pts4[p] = make_float4(x, y, z, fmaf(z, z, fmaf(y, y, x * x)));
    } else if (e < 192512) {
        int p = e - 180224;
        int jj = p >> 10, i = (p & 1023) >> 2, q = p & 3;
        g_w1p[p] = __ldg(&t1_w[i * 48 + jj * 4 + q]);
    } else if (e < 258048) {
        int p = e - 192512;
        int jj = p >> 10, i = (p & 1023) >> 2, q = p & 3;
        g_w2p[p] = __ldg(&t2_w[i * 256 + jj * 4 + q]);
    } else if (e < PREP_TOTAL) {
        int p = e - 258048;
        int jj = p >> 10, i = (p & 1023) >> 2, q = p & 3;
        g_w3p[p] = __ldg(&t3_w[i * 256 + jj * 4 + q]);
    }
}

// ---------------- kernel 2: kNN, warp-per-rep filter + flush ----------------
__device__ __forceinline__ u64 knn_pad(int s) {
    return 0xFFFFFFFF00000000ull | (unsigned)(0x40000000 + s);
}

__device__ __forceinline__ void knn_flush(u64* S, int lane) {
    __syncwarp();
    u64 k0 = S[lane], k1 = S[lane + 32];
    int r0 = 0, r1 = 0;
#pragma unroll
    for (int j = 0; j < 64; ++j) {
        u64 kj = S[j];
        r0 += (kj < k0); r1 += (kj < k1);
    }
    __syncwarp();
    S[r0] = k0; S[r1] = k1;       // ranks form a permutation (keys unique)
    __syncwarp();
    S[17 + lane] = knn_pad(17 + lane);
    if (lane < 15) S[49 + lane] = knn_pad(49 + lane);
    __syncwarp();
}

__global__ __launch_bounds__(512, 2) void knn_kernel(const int* __restrict__ rep_idx) {
    __shared__ u64 slots[16][64];
    const int tid = threadIdx.x;
    const int w = tid >> 5, lane = tid & 31;
    const int b = blockIdx.y;
    const int r = blockIdx.x * 16 + w;

    const int rpt = __ldg(&rep_idx[r]);
    const float4* P = g_pts4 + (size_t)b * NQ;
    const float4 rp = __ldg(&P[rpt]);

    u64* S = slots[w];
    S[lane] = knn_pad(lane);
    S[lane + 32] = knn_pad(lane + 32);
    __syncwarp();

    int cnt = 17;
    u64 tau = 0xFFFFFFFFFFFFFFFFull;

#pragma unroll 1
    for (int it = 0; it < 256; ++it) {
        const int c = (it << 5) + lane;
        const float4 q = __ldg(&P[c]);
        const float dot = fmaf(rp.z, q.z, fmaf(rp.y, q.y, rp.x * q.x));
        const float d2  = fmaf(-2.f, dot, rp.w + q.w);
        const unsigned s = __float_as_uint(d2);
        const unsigned u = (s & 0x80000000u) ? ~s : (s | 0x80000000u);
        const u64 key = ((u64)u << 32) | (unsigned)c;
        const bool pred = key < tau;
        const unsigned bal = __ballot_sync(0xffffffffu, pred);
        const int n = __popc(bal);
        if (cnt + n > 64) {
            knn_flush(S, lane);
            cnt = 17;
            tau = S[16];
        }
        if (pred) S[cnt + __popc(bal & ((1u << lane) - 1u))] = key;
        cnt += n;
    }
    if (cnt > 17) knn_flush(S, lane);

    if (lane < 16)
        g_nn[((size_t)b * RQ + r) * KQ + lane] =
            (int)(unsigned)(S[lane + 1] & 0xFFFFFFFFull);
}

// ---------------- kernel 3: gather + lift + T-net MLP + Tf, store Tf ----------------
#define MAIN_SMEM_FLOATS (4096 + 16 * 1288 + 768)
#define MAIN_SMEM_BYTES  (MAIN_SMEM_FLOATS * 4)
#define SF_OFF 4096
#define SP_OFF 24704

__global__ __launch_bounds__(256, 2) void mlp_kernel(
    const float* __restrict__ points,  const float* __restrict__ features,
    const float* __restrict__ lift_w,  const float* __restrict__ lift_b,
    const float* __restrict__ bnl_g,   const float* __restrict__ bnl_b,
    const float* __restrict__ t1_b,    const float* __restrict__ bn1_g,
    const float* __restrict__ bn1_b,   const float* __restrict__ t2_b,
    const float* __restrict__ bn2_g,   const float* __restrict__ bn2_b,
    const float* __restrict__ t3_b,    const float* __restrict__ bn3_g,
    const float* __restrict__ bn3_b,   const int* __restrict__ rep_idx,
    float* __restrict__ out_rep)
{
    extern __shared__ float sm[];
    float* sH = sm;
    float* sF = sm + SF_OFF;
    float* sP = sm + SP_OFF;
    const int tid = threadIdx.x;
    const int gg0 = blockIdx.x * 16;

    {
        const int g = tid >> 4, k = tid & 15;
        const int gg = gg0 + g;
        const int b = gg >> 11, rl = gg & 2047;
        const int rpt = __ldg(&rep_idx[rl]);
        const float* rpp = points + ((size_t)b * NQ + rpt) * 3;
        const float rx = __ldg(rpp), ry = __ldg(rpp + 1), rz = __ldg(rpp + 2);
        const int nb = g_nn[gg * KQ + k];
        const float* npp = points + ((size_t)b * NQ + nb) * 3;
        const float px = __ldg(npp) - rx, py = __ldg(npp + 1) - ry, pz = __ldg(npp + 2) - rz;
        sP[g * 48 + k * 3 + 0] = px;
        sP[g * 48 + k * 3 + 1] = py;
        sP[g * 48 + k * 3 + 2] = pz;
        if (k == 0) {
            out_rep[gg * 3 + 0] = rx; out_rep[gg * 3 + 1] = ry; out_rep[gg * 3 + 2] = rz;
        }
        float* fl = &sF[g * 1288 + k * 80];
#pragma unroll
        for (int j = 0; j < 16; j++) {
            float d = fmaf(pz, __ldg(&lift_w[j * 3 + 2]),
                      fmaf(py, __ldg(&lift_w[j * 3 + 1]), px * __ldg(&lift_w[j * 3 + 0])));
            float v = fmaf(d + __ldg(&lift_b[j]), __ldg(&bnl_g[j]), __ldg(&bnl_b[j]));
            fl[j] = fmaxf(v, 0.f);
        }
        const float4* fr = (const float4*)(features + ((size_t)b * NQ + nb) * 64);
        float4* fd = (float4*)(fl + 16);
#pragma unroll
        for (int q = 0; q < 16; q++) fd[q] = __ldg(fr + q);
    }
    __syncthreads();

    const int i = tid;
    u64 acc2[16];

    // ---- t1: pf[16][48] @ W1^T -> H[16][256], bn+relu (packed f32x2) ----
    {
#pragma unroll
        for (int g2 = 0; g2 < 16; g2++) acc2[g2] = 0ull;
#pragma unroll
        for (int jj = 0; jj < 12; ++jj) {
            const ulonglong2 w = __ldg((const ulonglong2*)&g_w1p[jj * 1024 + i * 4]);
#pragma unroll
            for (int g2 = 0; g2 < 16; ++g2) {
                const ulonglong2 h = *(const ulonglong2*)&sP[g2 * 48 + jj * 4];
                fma2(acc2[g2], w.x, h.x);
                fma2(acc2[g2], w.y, h.y);
            }
        }
        const float tb = __ldg(&t1_b[i]), bg = __ldg(&bn1_g[i]), bb = __ldg(&bn1_b[i]);
#pragma unroll
        for (int g2 = 0; g2 < 16; g2++) {
            const float2 v = up2(acc2[g2]);
            sH[g2 * 256 + i] = fmaxf(fmaf((v.x + v.y) + tb, bg, bb), 0.f);
        }
    }
    __syncthreads();

    // ---- t2: H @ W2^T, bn+relu (packed f32x2) ----
    {
#pragma unroll
        for (int g2 = 0; g2 < 16; g2++) acc2[g2] = 0ull;
#pragma unroll 4
        for (int jj = 0; jj < 64; ++jj) {
            const ulonglong2 w = __ldg((const ulonglong2*)&g_w2p[jj * 1024 + i * 4]);
#pragma unroll
            for (int g2 = 0; g2 < 16; ++g2) {
                const ulonglong2 h = *(const ulonglong2*)&sH[g2 * 256 + jj * 4];
                fma2(acc2[g2], w.x, h.x);
                fma2(acc2[g2], w.y, h.y);
            }
        }
        const float tb = __ldg(&t2_b[i]), bg = __ldg(&bn2_g[i]), bb = __ldg(&bn2_b[i]);
        __syncthreads();
#pragma unroll
        for (int g2 = 0; g2 < 16; g2++) {
            const float2 v = up2(acc2[g2]);
            sH[g2 * 256 + i] = fmaxf(fmaf((v.x + v.y) + tb, bg, bb), 0.f);
        }
    }
    __syncthreads();

    // ---- t3: H @ W3^T, bn (no relu) -> T[16][16][16] in sH (packed f32x2) ----
    {
#pragma unroll
        for (int g2 = 0; g2 < 16; g2++) acc2[g2] = 0ull;
#pragma unroll 4
        for (int jj = 0; jj < 64; ++jj) {
            const ulonglong2 w = __ldg((const ulonglong2*)&g_w3p[jj * 1024 + i * 4]);
#pragma unroll
            for (int g2 = 0; g2 < 16; ++g2) {
                const ulonglong2 h = *(const ulonglong2*)&sH[g2 * 256 + jj * 4];
                fma2(acc2[g2], w.x, h.x);
                fma2(acc2[g2], w.y, h.y);
            }
        }
        const float tb = __ldg(&t3_b[i]), bg = __ldg(&bn3_g[i]), bb = __ldg(&bn3_b[i]);
        __syncthreads();
#pragma unroll
        for (int g2 = 0; g2 < 16; g2++) {
            const float2 v = up2(acc2[g2]);
            sH[g2 * 256 + i] = fmaf((v.x + v.y) + tb, bg, bb);
        }
    }
    __syncthreads();

    const int aT = tid & 15, gT = tid >> 4;
    float tr[16];
#pragma unroll
    for (int q = 0; q < 4; q++) {
        const float4 v = *(const float4*)&sH[gT * 256 + aT * 16 + q * 4];
        tr[q * 4 + 0] = v.x; tr[q * 4 + 1] = v.y; tr[q * 4 + 2] = v.z; tr[q * 4 + 3] = v.w;
    }
    __syncthreads();

    // duplicated packs of T row for f32x2 Tf compute
    u64 trp[16];
#pragma unroll
    for (int k = 0; k < 16; k++) trp[k] = pk2(tr[k], tr[k]);

    const int gw = tid >> 4;
    const int ow = (tid & 15) * 16;
#pragma unroll 1
    for (int cb = 0; cb < 5; ++cb) {
#pragma unroll
        for (int q = 0; q < 4; q++) {
            const int c0 = cb * 16 + q * 4;
            u64 s01 = 0ull, s23 = 0ull;
#pragma unroll
            for (int k = 0; k < 16; k++) {
                const ulonglong2 f = *(const ulonglong2*)&sF[gT * 1288 + k * 80 + c0];
                fma2(s01, trp[k], f.x);
                fma2(s23, trp[k], f.y);
            }
            const float2 v01 = up2(s01), v23 = up2(s23);
            sH[gT * 256 + (q * 4 + 0) * 16 + aT] = v01.x;
            sH[gT * 256 + (q * 4 + 1) * 16 + aT] = v01.y;
            sH[gT * 256 + (q * 4 + 2) * 16 + aT] = v23.x;
            sH[gT * 256 + (q * 4 + 3) * 16 + aT] = v23.y;
        }
        __syncthreads();
        {
            float4* dst = (float4*)&g_tf[(size_t)(gg0 + gw) * 1280 + cb * 256 + ow];
            const float4* src = (const float4*)&sH[gw * 256 + ow];
            dst[0] = src[0]; dst[1] = src[1]; dst[2] = src[2]; dst[3] = src[3];
        }
        __syncthreads();
    }
}

// ---------------- kernel 4: conv GEMM, split-K x8, 128x128 tile, f32x2 ----------------
#define CV_KC   32
#define CV_SA_S 33
#define CONV_SMEM_BYTES ((128 * CV_SA_S + CV_KC * 128) * 4)

__global__ __launch_bounds__(256, 2) void conv_kernel(float* __restrict__ dummy) {
    extern __shared__ float sm[];
    float* sA = sm;                         // [128][33]  m-major
    float* sB = sm + 128 * CV_SA_S;         // [32][128]
    const int tid = threadIdx.x;
    const int gm0 = blockIdx.x * 128;
    const int kz  = blockIdx.y;
    const int k0z = kz * 160;

    const int tm = tid & 15;                // rows tm + 16*r
    const int tn = (tid >> 4) * 8;          // 8 cols

    u64 acc2[8][4];                          // [row][col-pair]
#pragma unroll
    for (int r = 0; r < 8; r++)
#pragma unroll
        for (int c = 0; c < 4; c++) acc2[r][c] = 0ull;

#pragma unroll 1
    for (int kt = 0; kt < 160; kt += CV_KC) {
        const int kbase = k0z + kt;
        // load B tile [32][128]: 1024 float4, 4 per thread
#pragma unroll
        for (int q = 0; q < 4; ++q) {
            int idx = tid + q * 256;
            int j = idx >> 5, c4 = idx & 31;
            *(float4*)&sB[j * 128 + c4 * 4] =
                __ldg((const float4*)&g_wt[(size_t)(kbase + j) * 128 + c4 * 4]);
        }
        // load A tile [128][32]: 1024 float4, 4 per thread (m-major, stride 33)
#pragma unroll
        for (int q = 0; q < 4; ++q) {
            int idx = tid + q * 256;
            int m = idx >> 3, k4 = idx & 7;
            float4 v = __ldg((const float4*)&g_tf[(size_t)(gm0 + m) * 1280 + kbase + k4 * 4]);
            float* d = &sA[m * CV_SA_S + k4 * 4];
            d[0] = v.x; d[1] = v.y; d[2] = v.z; d[3] = v.w;
        }
        __syncthreads();

#pragma unroll 2
        for (int k = 0; k < CV_KC; ++k) {
            const ulonglong2 b01 = *(const ulonglong2*)&sB[k * 128 + tn];
            const ulonglong2 b23 = *(const ulonglong2*)&sB[k * 128 + tn + 4];
            u64 ad[8];
#pragma unroll
            for (int r = 0; r < 8; r++) {
                const float a = sA[(tm + 16 * r) * CV_SA_S + k];
                ad[r] = pk2(a, a);
            }
#pragma unroll
            for (int r = 0; r < 8; r++) {
                fma2(acc2[r][0], ad[r], b01.x);
                fma2(acc2[r][1], ad[r], b01.y);
                fma2(acc2[r][2], ad[r], b23.x);
                fma2(acc2[r][3], ad[r], b23.y);
            }
        }
        __syncthreads();
    }

    float* dst = &g_part[kz][0];
#pragma unroll
    for (int r = 0; r < 8; r++) {
        const int m = gm0 + tm + 16 * r;
        const float2 c0 = up2(acc2[r][0]), c1 = up2(acc2[r][1]);
        const float2 c2 = up2(acc2[r][2]), c3 = up2(acc2[r][3]);
        *(float4*)&dst[(size_t)m * 128 + tn] = make_float4(c0.x, c0.y, c1.x, c1.y);
        *(float4*)&dst[(size_t)m * 128 + tn + 4] = make_float4(c2.x, c2.y, c3.x, c3.y);
    }
    (void)dummy;
}

// ---------------- kernel 5: split-K reduce + bias ----------------
__global__ void reduce_kernel(const float* __restrict__ conv_b,
                              float* __restrict__ out_main) {
    int t = blockIdx.x * 256 + threadIdx.x;      // float4 index, 131072 total
    int o4 = (t & 31) * 4;
    float4 s = *(const float4*)&g_part[0][(size_t)t * 4];
#pragma unroll
    for (int z = 1; z < 8; ++z) {
        const float4 p = *(const float4*)&g_part[z][(size_t)t * 4];
        s.x += p.x; s.y += p.y; s.z += p.z; s.w += p.w;
    }
    const float4 cb = __ldg((const float4*)&conv_b[o4]);
    s.x += cb.x; s.y += cb.y; s.z += cb.z; s.w += cb.w;
    *(float4*)&out_main[(size_t)t * 4] = s;
}

// ---------------- launch ----------------
extern "C" void kernel_launch(void* const* d_in, const int* in_sizes, int n_in,
                              void* d_out, int out_size) {
    (void)in_sizes; (void)n_in; (void)out_size;
    const float* points   = (const float*)d_in[0];
    const float* features = (const float*)d_in[1];
    const float* lift_w   = (const float*)d_in[2];
    const float* lift_b   = (const float*)d_in[3];
    const float* bnl_g    = (const float*)d_in[4];
    const float* bnl_b    = (const float*)d_in[5];
    const float* t1_w     = (const float*)d_in[6];
    const float* t1_b     = (const float*)d_in[7];
    const float* bn1_g    = (const float*)d_in[8];
    const float* bn1_b    = (const float*)d_in[9];
    const float* t2_w     = (const float*)d_in[10];
    const float* t2_b     = (const float*)d_in[11];
    const float* bn2_g    = (const float*)d_in[12];
    const float* bn2_b    = (const float*)d_in[13];
    const float* t3_w     = (const float*)d_in[14];
    const float* t3_b     = (const float*)d_in[15];
    const float* bn3_g    = (const float*)d_in[16];
    const float* bn3_b    = (const float*)d_in[17];
    const float* conv_w   = (const float*)d_in[18];
    const float* conv_b   = (const float*)d_in[19];
    const int*   rep_idx  = (const int*)d_in[20];

    float* out      = (float*)d_out;
    float* out_rep  = out;                       // [B][R][3]
    float* out_main = out + BQ * RQ * 3;         // [B][R][128]

    cudaFuncSetAttribute(mlp_kernel,  cudaFuncAttributeMaxDynamicSharedMemorySize, MAIN_SMEM_BYTES);
    cudaFuncSetAttribute(conv_kernel, cudaFuncAttributeMaxDynamicSharedMemorySize, CONV_SMEM_BYTES);

    prep_kernel<<<(PREP_TOTAL + 255) / 256, 256>>>(points, t1_w, t2_w, t3_w, conv_w);
    knn_kernel<<<dim3(128, 2), 512>>>(rep_idx);
    mlp_kernel<<<256, 256, MAIN_SMEM_BYTES>>>(
        points, features, lift_w, lift_b, bnl_g, bnl_b,
        t1_b, bn1_g, bn1_b, t2_b, bn2_g, bn2_b,
        t3_b, bn3_g, bn3_b, rep_idx, out_rep);
    conv_kernel<<<dim3(32, 8), 256, CONV_SMEM_BYTES>>>(nullptr);
    reduce_kernel<<<512, 256>>>(conv_b, out_main);
}

// round 11
// speedup vs baseline: 1.1508x; 1.1508x over previous
#include <cuda_runtime.h>
#include <cuda_bf16.h>
#include <cstdint>
#include <cfloat>
#include <cstddef>

#define BQ 2
#define NQ 8192
#define RQ 2048
#define KQ 16
#define COUTQ 128
#define GQ (BQ * RQ)

typedef unsigned long long u64;

// ---- packed fp32x2 helpers (MLP) ----
__device__ __forceinline__ u64 pk2(float lo, float hi) {
    u64 r;
    asm("mov.b64 %0, {%1, %2};" : "=l"(r)
        : "r"(__float_as_uint(lo)), "r"(__float_as_uint(hi)));
    return r;
}
__device__ __forceinline__ void fma2(u64& d, u64 a, u64 b) {
    asm("fma.rn.f32x2 %0, %1, %2, %0;" : "+l"(d) : "l"(a), "l"(b));
}
__device__ __forceinline__ float2 up2(u64 v) {
    unsigned lo, hi;
    asm("mov.b64 {%0, %1}, %2;" : "=r"(lo), "=r"(hi) : "l"(v));
    return make_float2(__uint_as_float(lo), __uint_as_float(hi));
}

// ---- mma.sync + cp.async helpers (baseline PTX, valid on sm_103) ----
__device__ __forceinline__ void mma16816(float* c, const unsigned* a, const unsigned* b) {
    asm volatile(
        "mma.sync.aligned.m16n8k16.row.col.f32.bf16.bf16.f32 "
        "{%0,%1,%2,%3}, {%4,%5,%6,%7}, {%8,%9}, {%0,%1,%2,%3};"
        : "+f"(c[0]), "+f"(c[1]), "+f"(c[2]), "+f"(c[3])
        : "r"(a[0]), "r"(a[1]), "r"(a[2]), "r"(a[3]), "r"(b[0]), "r"(b[1]));
}
__device__ __forceinline__ uint32_t smem_u32(const void* p) {
    uint32_t a;
    asm("{ .reg .u64 t; cvta.to.shared.u64 t, %1; cvt.u32.u64 %0, t; }"
        : "=r"(a) : "l"(p));
    return a;
}
__device__ __forceinline__ void cpa16(uint32_t s, const void* g) {
    asm volatile("cp.async.cg.shared.global [%0], [%1], 16;" :: "r"(s), "l"(g));
}

// ---------------- scratch (no allocations allowed) ----------------
__device__ int    g_nn[BQ * RQ * KQ];
__device__ float  g_w1p[12 * 1024];
__device__ float  g_w2p[64 * 1024];
__device__ float  g_w3p[64 * 1024];
__device__ float4 g_pts4[BQ * NQ];
__device__ __nv_bfloat16 g_ahi[(size_t)GQ * 1280];  // bf16 hi of Tf  [m][k]
__device__ __nv_bfloat16 g_alo[(size_t)GQ * 1280];  // bf16 lo of Tf
__device__ __nv_bfloat16 g_whi[COUTQ * 1280];       // bf16 hi of conv_w [o][j]
__device__ __nv_bfloat16 g_wlo[COUTQ * 1280];       // bf16 lo of conv_w
__device__ float  g_part[6][(size_t)GQ * COUTQ];    // split partials

// ---------------- kernel 1: prep ----------------
#define PREP_TOTAL 323584

__global__ void prep_kernel(const float* __restrict__ points,
                            const float* __restrict__ t1_w,
                            const float* __restrict__ t2_w,
                            const float* __restrict__ t3_w,
                            const float* __restrict__ conv_w) {
    int e = blockIdx.x * 256 + threadIdx.x;
    if (e < 163840) {
        float w = __ldg(&conv_w[e]);                 // [o][j] row-major, kept
        __nv_bfloat16 h = __float2bfloat16(w);
        g_whi[e] = h;
        g_wlo[e] = __float2bfloat16(w - __bfloat162float(h));
    } else if (e < 180224) {
        int p = e - 163840;
        const float* pp = points + (size_t)p * 3;
        float x = __ldg(pp), y = __ldg(pp + 1), z = __ldg(pp + 2);
        g_pts4[p] = make_float4(x, y, z, fmaf(z, z, fmaf(y, y, x * x)));
    } else if (e < 192512) {
        int p = e - 180224;
        int jj = p >> 10, i = (p & 1023) >> 2, q = p & 3;
        g_w1p[p] = __ldg(&t1_w[i * 48 + jj * 4 + q]);
    } else if (e < 258048) {
        int p = e - 192512;
        int jj = p >> 10, i = (p & 1023) >> 2, q = p & 3;
        g_w2p[p] = __ldg(&t2_w[i * 256 + jj * 4 + q]);
    } else if (e < PREP_TOTAL) {
        int p = e - 258048;
        int jj = p >> 10, i = (p & 1023) >> 2, q = p & 3;
        g_w3p[p] = __ldg(&t3_w[i * 256 + jj * 4 + q]);
    }
}

// ---------------- kernel 2: kNN (unchanged) ----------------
__device__ __forceinline__ u64 knn_pad(int s) {
    return 0xFFFFFFFF00000000ull | (unsigned)(0x40000000 + s);
}

__device__ __forceinline__ void knn_flush(u64* S, int lane) {
    __syncwarp();
    u64 k0 = S[lane], k1 = S[lane + 32];
    int r0 = 0, r1 = 0;
#pragma unroll
    for (int j = 0; j < 64; ++j) {
        u64 kj = S[j];
        r0 += (kj < k0); r1 += (kj < k1);
    }
    __syncwarp();
    S[r0] = k0; S[r1] = k1;
    __syncwarp();
    S[17 + lane] = knn_pad(17 + lane);
    if (lane < 15) S[49 + lane] = knn_pad(49 + lane);
    __syncwarp();
}

__global__ __launch_bounds__(512, 2) void knn_kernel(const int* __restrict__ rep_idx) {
    __shared__ u64 slots[16][64];
    const int tid = threadIdx.x;
    const int w = tid >> 5, lane = tid & 31;
    const int b = blockIdx.y;
    const int r = blockIdx.x * 16 + w;

    const int rpt = __ldg(&rep_idx[r]);
    const float4* P = g_pts4 + (size_t)b * NQ;
    const float4 rp = __ldg(&P[rpt]);

    u64* S = slots[w];
    S[lane] = knn_pad(lane);
    S[lane + 32] = knn_pad(lane + 32);
    __syncwarp();

    int cnt = 17;
    u64 tau = 0xFFFFFFFFFFFFFFFFull;

#pragma unroll 1
    for (int it = 0; it < 256; ++it) {
        const int c = (it << 5) + lane;
        const float4 q = __ldg(&P[c]);
        const float dot = fmaf(rp.z, q.z, fmaf(rp.y, q.y, rp.x * q.x));
        const float d2  = fmaf(-2.f, dot, rp.w + q.w);
        const unsigned s = __float_as_uint(d2);
        const unsigned u = (s & 0x80000000u) ? ~s : (s | 0x80000000u);
        const u64 key = ((u64)u << 32) | (unsigned)c;
        const bool pred = key < tau;
        const unsigned bal = __ballot_sync(0xffffffffu, pred);
        const int n = __popc(bal);
        if (cnt + n > 64) {
            knn_flush(S, lane);
            cnt = 17;
            tau = S[16];
        }
        if (pred) S[cnt + __popc(bal & ((1u << lane) - 1u))] = key;
        cnt += n;
    }
    if (cnt > 17) knn_flush(S, lane);

    if (lane < 16)
        g_nn[((size_t)b * RQ + r) * KQ + lane] =
            (int)(unsigned)(S[lane + 1] & 0xFFFFFFFFull);
}

// ---------------- kernel 3: gather + lift + T-net MLP + Tf -> bf16 hi/lo ----------------
#define MAIN_SMEM_FLOATS (4096 + 16 * 1288 + 768)
#define MAIN_SMEM_BYTES  (MAIN_SMEM_FLOATS * 4)
#define SF_OFF 4096
#define SP_OFF 24704

__global__ __launch_bounds__(256, 2) void mlp_kernel(
    const float* __restrict__ points,  const float* __restrict__ features,
    const float* __restrict__ lift_w,  const float* __restrict__ lift_b,
    const float* __restrict__ bnl_g,   const float* __restrict__ bnl_b,
    const float* __restrict__ t1_b,    const float* __restrict__ bn1_g,
    const float* __restrict__ bn1_b,   const float* __restrict__ t2_b,
    const float* __restrict__ bn2_g,   const float* __restrict__ bn2_b,
    const float* __restrict__ t3_b,    const float* __restrict__ bn3_g,
    const float* __restrict__ bn3_b,   const int* __restrict__ rep_idx,
    float* __restrict__ out_rep)
{
    extern __shared__ float sm[];
    float* sH = sm;
    float* sF = sm + SF_OFF;
    float* sP = sm + SP_OFF;
    const int tid = threadIdx.x;
    const int gg0 = blockIdx.x * 16;

    {
        const int g = tid >> 4, k = tid & 15;
        const int gg = gg0 + g;
        const int b = gg >> 11, rl = gg & 2047;
        const int rpt = __ldg(&rep_idx[rl]);
        const float* rpp = points + ((size_t)b * NQ + rpt) * 3;
        const float rx = __ldg(rpp), ry = __ldg(rpp + 1), rz = __ldg(rpp + 2);
        const int nb = g_nn[gg * KQ + k];
        const float* npp = points + ((size_t)b * NQ + nb) * 3;
        const float px = __ldg(npp) - rx, py = __ldg(npp + 1) - ry, pz = __ldg(npp + 2) - rz;
        sP[g * 48 + k * 3 + 0] = px;
        sP[g * 48 + k * 3 + 1] = py;
        sP[g * 48 + k * 3 + 2] = pz;
        if (k == 0) {
            out_rep[gg * 3 + 0] = rx; out_rep[gg * 3 + 1] = ry; out_rep[gg * 3 + 2] = rz;
        }
        float* fl = &sF[g * 1288 + k * 80];
#pragma unroll
        for (int j = 0; j < 16; j++) {
            float d = fmaf(pz, __ldg(&lift_w[j * 3 + 2]),
                      fmaf(py, __ldg(&lift_w[j * 3 + 1]), px * __ldg(&lift_w[j * 3 + 0])));
            float v = fmaf(d + __ldg(&lift_b[j]), __ldg(&bnl_g[j]), __ldg(&bnl_b[j]));
            fl[j] = fmaxf(v, 0.f);
        }
        const float4* fr = (const float4*)(features + ((size_t)b * NQ + nb) * 64);
        float4* fd = (float4*)(fl + 16);
#pragma unroll
        for (int q = 0; q < 16; q++) fd[q] = __ldg(fr + q);
    }
    __syncthreads();

    const int i = tid;
    u64 acc2[16];

    // ---- t1 ----
    {
#pragma unroll
        for (int g2 = 0; g2 < 16; g2++) acc2[g2] = 0ull;
#pragma unroll
        for (int jj = 0; jj < 12; ++jj) {
            const ulonglong2 w = __ldg((const ulonglong2*)&g_w1p[jj * 1024 + i * 4]);
#pragma unroll
            for (int g2 = 0; g2 < 16; ++g2) {
                const ulonglong2 h = *(const ulonglong2*)&sP[g2 * 48 + jj * 4];
                fma2(acc2[g2], w.x, h.x);
                fma2(acc2[g2], w.y, h.y);
            }
        }
        const float tb = __ldg(&t1_b[i]), bg = __ldg(&bn1_g[i]), bb = __ldg(&bn1_b[i]);
#pragma unroll
        for (int g2 = 0; g2 < 16; g2++) {
            const float2 v = up2(acc2[g2]);
            sH[g2 * 256 + i] = fmaxf(fmaf((v.x + v.y) + tb, bg, bb), 0.f);
        }
    }
    __syncthreads();

    // ---- t2 ----
    {
#pragma unroll
        for (int g2 = 0; g2 < 16; g2++) acc2[g2] = 0ull;
#pragma unroll 4
        for (int jj = 0; jj < 64; ++jj) {
            const ulonglong2 w = __ldg((const ulonglong2*)&g_w2p[jj * 1024 + i * 4]);
#pragma unroll
            for (int g2 = 0; g2 < 16; ++g2) {
                const ulonglong2 h = *(const ulonglong2*)&sH[g2 * 256 + jj * 4];
                fma2(acc2[g2], w.x, h.x);
                fma2(acc2[g2], w.y, h.y);
            }
        }
        const float tb = __ldg(&t2_b[i]), bg = __ldg(&bn2_g[i]), bb = __ldg(&bn2_b[i]);
        __syncthreads();
#pragma unroll
        for (int g2 = 0; g2 < 16; g2++) {
            const float2 v = up2(acc2[g2]);
            sH[g2 * 256 + i] = fmaxf(fmaf((v.x + v.y) + tb, bg, bb), 0.f);
        }
    }
    __syncthreads();

    // ---- t3 ----
    {
#pragma unroll
        for (int g2 = 0; g2 < 16; g2++) acc2[g2] = 0ull;
#pragma unroll 4
        for (int jj = 0; jj < 64; ++jj) {
            const ulonglong2 w = __ldg((const ulonglong2*)&g_w3p[jj * 1024 + i * 4]);
#pragma unroll
            for (int g2 = 0; g2 < 16; ++g2) {
                const ulonglong2 h = *(const ulonglong2*)&sH[g2 * 256 + jj * 4];
                fma2(acc2[g2], w.x, h.x);
                fma2(acc2[g2], w.y, h.y);
            }
        }
        const float tb = __ldg(&t3_b[i]), bg = __ldg(&bn3_g[i]), bb = __ldg(&bn3_b[i]);
        __syncthreads();
#pragma unroll
        for (int g2 = 0; g2 < 16; g2++) {
            const float2 v = up2(acc2[g2]);
            sH[g2 * 256 + i] = fmaf((v.x + v.y) + tb, bg, bb);
        }
    }
    __syncthreads();

    const int aT = tid & 15, gT = tid >> 4;
    float tr[16];
#pragma unroll
    for (int q = 0; q < 4; q++) {
        const float4 v = *(const float4*)&sH[gT * 256 + aT * 16 + q * 4];
        tr[q * 4 + 0] = v.x; tr[q * 4 + 1] = v.y; tr[q * 4 + 2] = v.z; tr[q * 4 + 3] = v.w;
    }
    __syncthreads();

    u64 trp[16];
#pragma unroll
    for (int k = 0; k < 16; k++) trp[k] = pk2(tr[k], tr[k]);

    const int gw = tid >> 4;
    const int ow = (tid & 15) * 16;
#pragma unroll 1
    for (int cb = 0; cb < 5; ++cb) {
#pragma unroll
        for (int q = 0; q < 4; q++) {
            const int c0 = cb * 16 + q * 4;
            u64 s01 = 0ull, s23 = 0ull;
#pragma unroll
            for (int k = 0; k < 16; k++) {
                const ulonglong2 f = *(const ulonglong2*)&sF[gT * 1288 + k * 80 + c0];
                fma2(s01, trp[k], f.x);
                fma2(s23, trp[k], f.y);
            }
            const float2 v01 = up2(s01), v23 = up2(s23);
            sH[gT * 256 + (q * 4 + 0) * 16 + aT] = v01.x;
            sH[gT * 256 + (q * 4 + 1) * 16 + aT] = v01.y;
            sH[gT * 256 + (q * 4 + 2) * 16 + aT] = v23.x;
            sH[gT * 256 + (q * 4 + 3) * 16 + aT] = v23.y;
        }
        __syncthreads();
        {
            const float* src = &sH[gw * 256 + ow];
            __align__(16) __nv_bfloat16 hv[16], lv[16];
#pragma unroll
            for (int i2 = 0; i2 < 16; i2++) {
                const float v = src[i2];
                const __nv_bfloat16 h = __float2bfloat16(v);
                hv[i2] = h;
                lv[i2] = __float2bfloat16(v - __bfloat162float(h));
            }
            const size_t off = (size_t)(gg0 + gw) * 1280 + cb * 256 + ow;
            *(uint4*)&g_ahi[off]     = *(const uint4*)&hv[0];
            *(uint4*)&g_ahi[off + 8] = *(const uint4*)&hv[8];
            *(uint4*)&g_alo[off]     = *(const uint4*)&lv[0];
            *(uint4*)&g_alo[off + 8] = *(const uint4*)&lv[8];
        }
        __syncthreads();
    }
}

// ---------------- kernel 4: conv GEMM via mma.sync (bf16 split-3, fp32 acc) ----------------
// grid (64, 6): blockIdx.x = 64-row M tile; blockIdx.y = s:
//   product p = s>>1 in {hi*hi, hi*lo, lo*hi}, K half = s&1 (640 each).
// 128 threads / 4 warps; warp tile 32m x 64n; K chunk 64, cp.async double buffer.
#define CV_AS    72                         // smem row stride in bf16
#define CV_ATILE (64 * CV_AS)               // 4608
#define CV_BUF   (CV_ATILE + 128 * CV_AS)   // 13824 bf16 per buffer
#define CV_SMEM_BYTES (2 * CV_BUF * 2)      // 55296 B

__global__ __launch_bounds__(128) void conv_mma_kernel() {
    extern __shared__ __nv_bfloat16 smb[];
    const int tid = threadIdx.x;
    const int w = tid >> 5, lane = tid & 31;
    const int gm0 = blockIdx.x * 64;
    const int s = blockIdx.y;
    const int p = s >> 1;
    const int koff0 = (s & 1) * 640;

    const __nv_bfloat16* Asrc = (p == 2) ? g_alo : g_ahi;
    const __nv_bfloat16* Bsrc = (p == 1) ? g_wlo : g_whi;

    const int wm = (w & 1) * 32;
    const int wn = (w >> 1) * 64;

    float acc[2][8][4];
#pragma unroll
    for (int mt = 0; mt < 2; mt++)
#pragma unroll
        for (int nt = 0; nt < 8; nt++)
#pragma unroll
            for (int q = 0; q < 4; q++) acc[mt][nt][q] = 0.f;

    // staging indices (per thread): A 4 x 16B, B 8 x 16B per chunk
    const uint32_t sbase = smem_u32(smb);
    int a_row[4], a_c8[4], b_row[8], b_c8[8];
#pragma unroll
    for (int q = 0; q < 4; q++) {
        const int i2 = tid + q * 128;
        a_row[q] = i2 >> 3; a_c8[q] = (i2 & 7) * 8;
    }
#pragma unroll
    for (int q = 0; q < 8; q++) {
        const int i2 = tid + q * 128;
        b_row[q] = i2 >> 3; b_c8[q] = (i2 & 7) * 8;
    }

#define CV_STAGE(cidx, buf) do {                                               \
    const int _ko = koff0 + (cidx) * 64;                                       \
    const uint32_t _sb = sbase + (buf) * (CV_BUF * 2);                         \
    _Pragma("unroll")                                                          \
    for (int q = 0; q < 4; q++)                                                \
        cpa16(_sb + (a_row[q] * CV_AS + a_c8[q]) * 2,                          \
              &Asrc[(size_t)(gm0 + a_row[q]) * 1280 + _ko + a_c8[q]]);         \
    _Pragma("unroll")                                                          \
    for (int q = 0; q < 8; q++)                                                \
        cpa16(_sb + (CV_ATILE + b_row[q] * CV_AS + b_c8[q]) * 2,               \
              &Bsrc[(size_t)b_row[q] * 1280 + _ko + b_c8[q]]);                 \
    asm volatile("cp.async.commit_group;");                                    \
} while (0)

    CV_STAGE(0, 0);

#pragma unroll 1
    for (int c = 0; c < 10; ++c) {
        if (c < 9) CV_STAGE(c + 1, (c + 1) & 1);
        if (c < 9) asm volatile("cp.async.wait_group 1;");
        else       asm volatile("cp.async.wait_group 0;");
        __syncthreads();

        const __nv_bfloat16* sA = smb + (c & 1) * CV_BUF;
        const __nv_bfloat16* sB = sA + CV_ATILE;

#pragma unroll
        for (int kb = 0; kb < 64; kb += 16) {
            unsigned bfr[8][2];
#pragma unroll
            for (int nt = 0; nt < 8; nt++) {
                const int base = (wn + nt * 8 + (lane >> 2)) * CV_AS + kb + (lane & 3) * 2;
                bfr[nt][0] = *(const unsigned*)&sB[base];
                bfr[nt][1] = *(const unsigned*)&sB[base + 8];
            }
            unsigned afr[2][4];
#pragma unroll
            for (int mt = 0; mt < 2; mt++) {
                const int base = (wm + mt * 16 + (lane >> 2)) * CV_AS + kb + (lane & 3) * 2;
                afr[mt][0] = *(const unsigned*)&sA[base];
                afr[mt][1] = *(const unsigned*)&sA[base + 8 * CV_AS];
                afr[mt][2] = *(const unsigned*)&sA[base + 8];
                afr[mt][3] = *(const unsigned*)&sA[base + 8 * CV_AS + 8];
            }
#pragma unroll
            for (int mt = 0; mt < 2; mt++)
#pragma unroll
                for (int nt = 0; nt < 8; nt++)
                    mma16816(acc[mt][nt], afr[mt], bfr[nt]);
        }
        __syncthreads();
    }

    // epilogue -> partials
    float* dst = &g_part[s][0];
#pragma unroll
    for (int mt = 0; mt < 2; mt++) {
        const int m0 = gm0 + wm + mt * 16 + (lane >> 2);
#pragma unroll
        for (int nt = 0; nt < 8; nt++) {
            const int n0 = wn + nt * 8 + (lane & 3) * 2;
            *(float2*)&dst[(size_t)m0 * 128 + n0] = make_float2(acc[mt][nt][0], acc[mt][nt][1]);
            *(float2*)&dst[(size_t)(m0 + 8) * 128 + n0] = make_float2(acc[mt][nt][2], acc[mt][nt][3]);
        }
    }
}

// ---------------- kernel 5: reduce 6 partials + bias ----------------
__global__ void reduce_kernel(const float* __restrict__ conv_b,
                              float* __restrict__ out_main) {
    int t = blockIdx.x * 256 + threadIdx.x;      // float4 index, 131072 total
    int o4 = (t & 31) * 4;
    float4 s = *(const float4*)&g_part[0][(size_t)t * 4];
#pragma unroll
    for (int z = 1; z < 6; ++z) {
        const float4 p = *(const float4*)&g_part[z][(size_t)t * 4];
        s.x += p.x; s.y += p.y; s.z += p.z; s.w += p.w;
    }
    const float4 cb = __ldg((const float4*)&conv_b[o4]);
    s.x += cb.x; s.y += cb.y; s.z += cb.z; s.w += cb.w;
    *(float4*)&out_main[(size_t)t * 4] = s;
}

// ---------------- launch ----------------
extern "C" void kernel_launch(void* const* d_in, const int* in_sizes, int n_in,
                              void* d_out, int out_size) {
    (void)in_sizes; (void)n_in; (void)out_size;
    const float* points   = (const float*)d_in[0];
    const float* features = (const float*)d_in[1];
    const float* lift_w   = (const float*)d_in[2];
    const float* lift_b   = (const float*)d_in[3];
    const float* bnl_g    = (const float*)d_in[4];
    const float* bnl_b    = (const float*)d_in[5];
    const float* t1_w     = (const float*)d_in[6];
    const float* t1_b     = (const float*)d_in[7];
    const float* bn1_g    = (const float*)d_in[8];
    const float* bn1_b    = (const float*)d_in[9];
    const float* t2_w     = (const float*)d_in[10];
    const float* t2_b     = (const float*)d_in[11];
    const float* bn2_g    = (const float*)d_in[12];
    const float* bn2_b    = (const float*)d_in[13];
    const float* t3_w     = (const float*)d_in[14];
    const float* t3_b     = (const float*)d_in[15];
    const float* bn3_g    = (const float*)d_in[16];
    const float* bn3_b    = (const float*)d_in[17];
    const float* conv_w   = (const float*)d_in[18];
    const float* conv_b   = (const float*)d_in[19];
    const int*   rep_idx  = (const int*)d_in[20];

    float* out      = (float*)d_out;
    float* out_rep  = out;                       // [B][R][3]
    float* out_main = out + BQ * RQ * 3;         // [B][R][128]

    cudaFuncSetAttribute(mlp_kernel, cudaFuncAttributeMaxDynamicSharedMemorySize, MAIN_SMEM_BYTES);
    cudaFuncSetAttribute(conv_mma_kernel, cudaFuncAttributeMaxDynamicSharedMemorySize, CV_SMEM_BYTES);

    prep_kernel<<<(PREP_TOTAL + 255) / 256, 256>>>(points, t1_w, t2_w, t3_w, conv_w);
    knn_kernel<<<dim3(128, 2), 512>>>(rep_idx);
    mlp_kernel<<<256, 256, MAIN_SMEM_BYTES>>>(
        points, features, lift_w, lift_b, bnl_g, bnl_b,
        t1_b, bn1_g, bn1_b, t2_b, bn2_g, bn2_b,
        t3_b, bn3_g, bn3_b, rep_idx, out_rep);
    conv_mma_kernel<<<dim3(64, 6), 128, CV_SMEM_BYTES>>>();
    reduce_kernel<<<512, 256>>>(conv_b, out_main);
}

// round 14
// speedup vs baseline: 1.2243x; 1.0639x over previous
#include <cuda_runtime.h>
#include <cuda_bf16.h>
#include <cstdint>
#include <cfloat>
#include <cstddef>

#define BQ 2
#define NQ 8192
#define RQ 2048
#define KQ 16
#define COUTQ 128
#define GQ (BQ * RQ)

typedef unsigned long long u64;

// ---- packed fp32x2 helpers (tf kernel) ----
__device__ __forceinline__ u64 pk2(float lo, float hi) {
    u64 r;
    asm("mov.b64 %0, {%1, %2};" : "=l"(r)
        : "r"(__float_as_uint(lo)), "r"(__float_as_uint(hi)));
    return r;
}
__device__ __forceinline__ void fma2(u64& d, u64 a, u64 b) {
    asm("fma.rn.f32x2 %0, %1, %2, %0;" : "+l"(d) : "l"(a), "l"(b));
}
__device__ __forceinline__ float2 up2(u64 v) {
    unsigned lo, hi;
    asm("mov.b64 {%0, %1}, %2;" : "=r"(lo), "=r"(hi) : "l"(v));
    return make_float2(__uint_as_float(lo), __uint_as_float(hi));
}

// ---- mma.sync + cp.async helpers ----
__device__ __forceinline__ void mma16816(float* c, const unsigned* a, const unsigned* b) {
    asm volatile(
        "mma.sync.aligned.m16n8k16.row.col.f32.bf16.bf16.f32 "
        "{%0,%1,%2,%3}, {%4,%5,%6,%7}, {%8,%9}, {%0,%1,%2,%3};"
        : "+f"(c[0]), "+f"(c[1]), "+f"(c[2]), "+f"(c[3])
        : "r"(a[0]), "r"(a[1]), "r"(a[2]), "r"(a[3]), "r"(b[0]), "r"(b[1]));
}
__device__ __forceinline__ uint32_t smem_u32(const void* p) {
    uint32_t a;
    asm("{ .reg .u64 t; cvta.to.shared.u64 t, %1; cvt.u32.u64 %0, t; }"
        : "=r"(a) : "l"(p));
    return a;
}
__device__ __forceinline__ void cpa16(uint32_t s, const void* g) {
    asm volatile("cp.async.cg.shared.global [%0], [%1], 16;" :: "r"(s), "l"(g));
}
__device__ __forceinline__ void bf16split(float v, __nv_bfloat16& h, __nv_bfloat16& l) {
    h = __float2bfloat16(v);
    l = __float2bfloat16(v - __bfloat162float(h));
}

// ---------------- scratch (no allocations allowed) ----------------
__device__ int    g_nn[BQ * RQ * KQ];
__device__ float4 g_pts4[BQ * NQ];
__device__ __nv_bfloat16 g_pf_hi[GQ * 64],  g_pf_lo[GQ * 64];    // PF, K padded 48->64
__device__ __nv_bfloat16 g_w1hi[256 * 64],  g_w1lo[256 * 64];    // t1_w padded
__device__ __nv_bfloat16 g_w2hi[256 * 256], g_w2lo[256 * 256];
__device__ __nv_bfloat16 g_w3hi[256 * 256], g_w3lo[256 * 256];
__device__ __nv_bfloat16 g_h1hi[(size_t)GQ * 256], g_h1lo[(size_t)GQ * 256];
__device__ __nv_bfloat16 g_h2hi[(size_t)GQ * 256], g_h2lo[(size_t)GQ * 256];
__device__ float  g_T[(size_t)GQ * 256];
__device__ __nv_bfloat16 g_ahi[(size_t)GQ * 1280], g_alo[(size_t)GQ * 1280];
__device__ __nv_bfloat16 g_whi[COUTQ * 1280], g_wlo[COUTQ * 1280];
__device__ float  g_part[6][(size_t)GQ * COUTQ];

// ---------------- kernel 1: prep ----------------
#define PREP_TOTAL 327680

__global__ void prep_kernel(const float* __restrict__ points,
                            const float* __restrict__ t1_w,
                            const float* __restrict__ t2_w,
                            const float* __restrict__ t3_w,
                            const float* __restrict__ conv_w) {
    int e = blockIdx.x * 256 + threadIdx.x;
    if (e < 163840) {
        bf16split(__ldg(&conv_w[e]), g_whi[e], g_wlo[e]);
    } else if (e < 180224) {
        int p = e - 163840;
        const float* pp = points + (size_t)p * 3;
        float x = __ldg(pp), y = __ldg(pp + 1), z = __ldg(pp + 2);
        g_pts4[p] = make_float4(x, y, z, fmaf(z, z, fmaf(y, y, x * x)));
    } else if (e < 196608) {
        int p = e - 180224;
        int n = p >> 6, j = p & 63;
        float v = (j < 48) ? __ldg(&t1_w[n * 48 + j]) : 0.f;
        bf16split(v, g_w1hi[p], g_w1lo[p]);
    } else if (e < 262144) {
        int p = e - 196608;
        bf16split(__ldg(&t2_w[p]), g_w2hi[p], g_w2lo[p]);
    } else if (e < PREP_TOTAL) {
        int p = e - 262144;
        bf16split(__ldg(&t3_w[p]), g_w3hi[p], g_w3lo[p]);
    }
}

// ---------------- kernel 2: kNN (proven) ----------------
__device__ __forceinline__ u64 knn_pad(int s) {
    return 0xFFFFFFFF00000000ull | (unsigned)(0x40000000 + s);
}

__device__ __forceinline__ void knn_flush(u64* S, int lane) {
    __syncwarp();
    u64 k0 = S[lane], k1 = S[lane + 32];
    int r0 = 0, r1 = 0;
#pragma unroll
    for (int j = 0; j < 64; ++j) {
        u64 kj = S[j];
        r0 += (kj < k0); r1 += (kj < k1);
    }
    __syncwarp();
    S[r0] = k0; S[r1] = k1;
    __syncwarp();
    S[17 + lane] = knn_pad(17 + lane);
    if (lane < 15) S[49 + lane] = knn_pad(49 + lane);
    __syncwarp();
}

__global__ __launch_bounds__(512, 2) void knn_kernel(const int* __restrict__ rep_idx) {
    __shared__ u64 slots[16][64];
    const int tid = threadIdx.x;
    const int w = tid >> 5, lane = tid & 31;
    const int b = blockIdx.y;
    const int r = blockIdx.x * 16 + w;

    const int rpt = __ldg(&rep_idx[r]);
    const float4* P = g_pts4 + (size_t)b * NQ;
    const float4 rp = __ldg(&P[rpt]);

    u64* S = slots[w];
    S[lane] = knn_pad(lane);
    S[lane + 32] = knn_pad(lane + 32);
    __syncwarp();

    int cnt = 17;
    u64 tau = 0xFFFFFFFFFFFFFFFFull;

#pragma unroll 1
    for (int it = 0; it < 256; ++it) {
        const int c = (it << 5) + lane;
        const float4 q = __ldg(&P[c]);
        const float dot = fmaf(rp.z, q.z, fmaf(rp.y, q.y, rp.x * q.x));
        const float d2  = fmaf(-2.f, dot, rp.w + q.w);
        const unsigned s = __float_as_uint(d2);
        const unsigned u = (s & 0x80000000u) ? ~s : (s | 0x80000000u);
        const u64 key = ((u64)u << 32) | (unsigned)c;
        const bool pred = key < tau;
        const unsigned bal = __ballot_sync(0xffffffffu, pred);
        const int n = __popc(bal);
        if (cnt + n > 64) {
            knn_flush(S, lane);
            cnt = 17;
            tau = S[16];
        }
        if (pred) S[cnt + __popc(bal & ((1u << lane) - 1u))] = key;
        cnt += n;
    }
    if (cnt > 17) knn_flush(S, lane);

    if (lane < 16)
        g_nn[((size_t)b * RQ + r) * KQ + lane] =
            (int)(unsigned)(S[lane + 1] & 0xFFFFFFFFull);
}

// ---------------- kernel 3: gather PF (padded K=64) + rep_pos ----------------
__global__ __launch_bounds__(256) void gatherpf_kernel(
    const float* __restrict__ points, const int* __restrict__ rep_idx,
    float* __restrict__ out_rep)
{
    const int tid = threadIdx.x;
    const int g = tid >> 4, k = tid & 15;
    const int gg = blockIdx.x * 16 + g;
    const int b = gg >> 11, rl = gg & 2047;
    const int rpt = __ldg(&rep_idx[rl]);
    const float* rpp = points + ((size_t)b * NQ + rpt) * 3;
    const float rx = __ldg(rpp), ry = __ldg(rpp + 1), rz = __ldg(rpp + 2);
    const int nb = g_nn[gg * KQ + k];
    const float* npp = points + ((size_t)b * NQ + nb) * 3;
    const float pv[3] = { __ldg(npp) - rx, __ldg(npp + 1) - ry, __ldg(npp + 2) - rz };
#pragma unroll
    for (int i = 0; i < 3; i++) {
        __nv_bfloat16 h, l;
        bf16split(pv[i], h, l);
        g_pf_hi[gg * 64 + k * 3 + i] = h;
        g_pf_lo[gg * 64 + k * 3 + i] = l;
    }
    if (k < 8) {   // zero pad j in [48,64)
        const __nv_bfloat16 z = __float2bfloat16(0.f);
        g_pf_hi[gg * 64 + 48 + k * 2 + 0] = z;
        g_pf_hi[gg * 64 + 48 + k * 2 + 1] = z;
        g_pf_lo[gg * 64 + 48 + k * 2 + 0] = z;
        g_pf_lo[gg * 64 + 48 + k * 2 + 1] = z;
    }
    if (k == 0) {
        out_rep[gg * 3 + 0] = rx; out_rep[gg * 3 + 1] = ry; out_rep[gg * 3 + 2] = rz;
    }
}

// ---------------- kernel 4: T-net GEMM (device-side operand selection) ----------------
// stage 0: PF @ W1 -> h1 (relu)   KD=64,  niter=3,  cl2=0
// stage 1: h1 @ W2 -> h2 (relu)   KD=256, niter=12, cl2=2
// stage 2: h2 @ W3 -> T  (fp32)   KD=256, niter=12, cl2=2
#define GS_AS    72
#define GS_ATILE (64 * GS_AS)
#define GS_BUF   (GS_ATILE + 128 * GS_AS)
#define GS_SMEM_BYTES (2 * GS_BUF * 2)

__global__ __launch_bounds__(128) void gemm_tnet(
    int stage,
    const float* __restrict__ bias, const float* __restrict__ bng,
    const float* __restrict__ bnb,
    int KD, int niter, int cl2, int relu)
{
    // resolve operands from device symbols (host cannot pass their addresses)
    const __nv_bfloat16 *Ahi, *Alo, *Bhi, *Blo;
    __nv_bfloat16 *Ohi = nullptr, *Olo = nullptr;
    float* Of32 = nullptr;
    if (stage == 0) {
        Ahi = g_pf_hi; Alo = g_pf_lo; Bhi = g_w1hi; Blo = g_w1lo;
        Ohi = g_h1hi;  Olo = g_h1lo;
    } else if (stage == 1) {
        Ahi = g_h1hi;  Alo = g_h1lo;  Bhi = g_w2hi; Blo = g_w2lo;
        Ohi = g_h2hi;  Olo = g_h2lo;
    } else {
        Ahi = g_h2hi;  Alo = g_h2lo;  Bhi = g_w3hi; Blo = g_w3lo;
        Of32 = g_T;
    }

    extern __shared__ __nv_bfloat16 smb[];
    const int tid = threadIdx.x;
    const int w = tid >> 5, lane = tid & 31;
    const int gm0 = blockIdx.x * 64;
    const int gn0 = blockIdx.y * 128;
    const int wm = (w & 1) * 32;
    const int wn = (w >> 1) * 64;

    float acc[2][8][4];
#pragma unroll
    for (int mt = 0; mt < 2; mt++)
#pragma unroll
        for (int nt = 0; nt < 8; nt++)
#pragma unroll
            for (int q = 0; q < 4; q++) acc[mt][nt][q] = 0.f;

    const uint32_t sbase = smem_u32(smb);

#define TN_STAGE(cidx, buf) do {                                               \
    const int _p = (cidx) >> cl2;                                              \
    const int _ko = ((cidx) & ((1 << cl2) - 1)) << 6;                          \
    const __nv_bfloat16* _As = (_p == 2) ? Alo : Ahi;                          \
    const __nv_bfloat16* _Bs = (_p == 1) ? Blo : Bhi;                          \
    const uint32_t _sb = sbase + (buf) * (GS_BUF * 2);                         \
    _Pragma("unroll")                                                          \
    for (int q = 0; q < 4; q++) {                                              \
        const int i2 = tid + q * 128;                                          \
        const int row = i2 >> 3, c8 = (i2 & 7) * 8;                            \
        cpa16(_sb + (row * GS_AS + c8) * 2,                                    \
              &_As[(size_t)(gm0 + row) * KD + _ko + c8]);                      \
    }                                                                          \
    _Pragma("unroll")                                                          \
    for (int q = 0; q < 8; q++) {                                              \
        const int i2 = tid + q * 128;                                          \
        const int row = i2 >> 3, c8 = (i2 & 7) * 8;                            \
        cpa16(_sb + (GS_ATILE + row * GS_AS + c8) * 2,                         \
              &_Bs[(size_t)(gn0 + row) * KD + _ko + c8]);                      \
    }                                                                          \
    asm volatile("cp.async.commit_group;");                                    \
} while (0)

    TN_STAGE(0, 0);

#pragma unroll 1
    for (int c = 0; c < niter; ++c) {
        if (c < niter - 1) {
            TN_STAGE(c + 1, (c + 1) & 1);
            asm volatile("cp.async.wait_group 1;");
        } else {
            asm volatile("cp.async.wait_group 0;");
        }
        __syncthreads();

        const __nv_bfloat16* sA = smb + (c & 1) * GS_BUF;
        const __nv_bfloat16* sB = sA + GS_ATILE;

#pragma unroll
        for (int kb = 0; kb < 64; kb += 16) {
            unsigned bfr[8][2];
#pragma unroll
            for (int nt = 0; nt < 8; nt++) {
                const int base = (wn + nt * 8 + (lane >> 2)) * GS_AS + kb + (lane & 3) * 2;
                bfr[nt][0] = *(const unsigned*)&sB[base];
                bfr[nt][1] = *(const unsigned*)&sB[base + 8];
            }
            unsigned afr[2][4];
#pragma unroll
            for (int mt = 0; mt < 2; mt++) {
                const int base = (wm + mt * 16 + (lane >> 2)) * GS_AS + kb + (lane & 3) * 2;
                afr[mt][0] = *(const unsigned*)&sA[base];
                afr[mt][1] = *(const unsigned*)&sA[base + 8 * GS_AS];
                afr[mt][2] = *(const unsigned*)&sA[base + 8];
                afr[mt][3] = *(const unsigned*)&sA[base + 8 * GS_AS + 8];
            }
#pragma unroll
            for (int mt = 0; mt < 2; mt++)
#pragma unroll
                for (int nt = 0; nt < 8; nt++)
                    mma16816(acc[mt][nt], afr[mt], bfr[nt]);
        }
        __syncthreads();
    }

    const bool f32mode = (stage == 2);
#pragma unroll
    for (int mt = 0; mt < 2; mt++) {
        const int m0 = gm0 + wm + mt * 16 + (lane >> 2);
#pragma unroll
        for (int nt = 0; nt < 8; nt++) {
            const int n0 = gn0 + wn + nt * 8 + (lane & 3) * 2;
            const float2 bs = *(const float2*)&bias[n0];
            const float2 gv = *(const float2*)&bng[n0];
            const float2 bv = *(const float2*)&bnb[n0];
            float v00 = fmaf(acc[mt][nt][0] + bs.x, gv.x, bv.x);
            float v01 = fmaf(acc[mt][nt][1] + bs.y, gv.y, bv.y);
            float v10 = fmaf(acc[mt][nt][2] + bs.x, gv.x, bv.x);
            float v11 = fmaf(acc[mt][nt][3] + bs.y, gv.y, bv.y);
            if (relu) {
                v00 = fmaxf(v00, 0.f); v01 = fmaxf(v01, 0.f);
                v10 = fmaxf(v10, 0.f); v11 = fmaxf(v11, 0.f);
            }
            if (f32mode) {
                *(float2*)&Of32[(size_t)m0 * 256 + n0] = make_float2(v00, v01);
                *(float2*)&Of32[(size_t)(m0 + 8) * 256 + n0] = make_float2(v10, v11);
            } else {
                __nv_bfloat16 h0, l0, h1, l1;
                bf16split(v00, h0, l0); bf16split(v01, h1, l1);
                *(__nv_bfloat162*)&Ohi[(size_t)m0 * 256 + n0] = __halves2bfloat162(h0, h1);
                *(__nv_bfloat162*)&Olo[(size_t)m0 * 256 + n0] = __halves2bfloat162(l0, l1);
                bf16split(v10, h0, l0); bf16split(v11, h1, l1);
                *(__nv_bfloat162*)&Ohi[(size_t)(m0 + 8) * 256 + n0] = __halves2bfloat162(h0, h1);
                *(__nv_bfloat162*)&Olo[(size_t)(m0 + 8) * 256 + n0] = __halves2bfloat162(l0, l1);
            }
        }
    }
}

// ---------------- kernel 5: gather feat + lift + Tf -> bf16 hi/lo ----------------
#define TF_SMEM_FLOATS (4096 + 16 * 1288)
#define TF_SMEM_BYTES  (TF_SMEM_FLOATS * 4)
#define SF_OFF 4096

__global__ __launch_bounds__(256, 2) void tf_kernel(
    const float* __restrict__ points,  const float* __restrict__ features,
    const float* __restrict__ lift_w,  const float* __restrict__ lift_b,
    const float* __restrict__ bnl_g,   const float* __restrict__ bnl_b,
    const int* __restrict__ rep_idx)
{
    extern __shared__ float sm[];
    float* sH = sm;
    float* sF = sm + SF_OFF;
    const int tid = threadIdx.x;
    const int gg0 = blockIdx.x * 16;

    {
        const int g = tid >> 4, k = tid & 15;
        const int gg = gg0 + g;
        const int b = gg >> 11, rl = gg & 2047;
        const int rpt = __ldg(&rep_idx[rl]);
        const float* rpp = points + ((size_t)b * NQ + rpt) * 3;
        const float rx = __ldg(rpp), ry = __ldg(rpp + 1), rz = __ldg(rpp + 2);
        const int nb = g_nn[gg * KQ + k];
        const float* npp = points + ((size_t)b * NQ + nb) * 3;
        const float px = __ldg(npp) - rx, py = __ldg(npp + 1) - ry, pz = __ldg(npp + 2) - rz;
        float* fl = &sF[g * 1288 + k * 80];
#pragma unroll
        for (int j = 0; j < 16; j++) {
            float d = fmaf(pz, __ldg(&lift_w[j * 3 + 2]),
                      fmaf(py, __ldg(&lift_w[j * 3 + 1]), px * __ldg(&lift_w[j * 3 + 0])));
            float v = fmaf(d + __ldg(&lift_b[j]), __ldg(&bnl_g[j]), __ldg(&bnl_b[j]));
            fl[j] = fmaxf(v, 0.f);
        }
        const float4* fr = (const float4*)(features + ((size_t)b * NQ + nb) * 64);
        float4* fd = (float4*)(fl + 16);
#pragma unroll
        for (int q = 0; q < 16; q++) fd[q] = __ldg(fr + q);
    }
    __syncthreads();

    const int aT = tid & 15, gT = tid >> 4;
    u64 trp[16];
#pragma unroll
    for (int q = 0; q < 4; q++) {
        const float4 v = __ldg((const float4*)&g_T[(size_t)(gg0 + gT) * 256 + aT * 16 + q * 4]);
        trp[q * 4 + 0] = pk2(v.x, v.x); trp[q * 4 + 1] = pk2(v.y, v.y);
        trp[q * 4 + 2] = pk2(v.z, v.z); trp[q * 4 + 3] = pk2(v.w, v.w);
    }

    const int gw = tid >> 4;
    const int ow = (tid & 15) * 16;
#pragma unroll 1
    for (int cb = 0; cb < 5; ++cb) {
#pragma unroll
        for (int q = 0; q < 4; q++) {
            const int c0 = cb * 16 + q * 4;
            u64 s01 = 0ull, s23 = 0ull;
#pragma unroll
            for (int k = 0; k < 16; k++) {
                const ulonglong2 f = *(const ulonglong2*)&sF[gT * 1288 + k * 80 + c0];
                fma2(s01, trp[k], f.x);
                fma2(s23, trp[k], f.y);
            }
            const float2 v01 = up2(s01), v23 = up2(s23);
            sH[gT * 256 + (q * 4 + 0) * 16 + aT] = v01.x;
            sH[gT * 256 + (q * 4 + 1) * 16 + aT] = v01.y;
            sH[gT * 256 + (q * 4 + 2) * 16 + aT] = v23.x;
            sH[gT * 256 + (q * 4 + 3) * 16 + aT] = v23.y;
        }
        __syncthreads();
        {
            const float* src = &sH[gw * 256 + ow];
            __align__(16) __nv_bfloat16 hv[16], lv[16];
#pragma unroll
            for (int i2 = 0; i2 < 16; i2++) bf16split(src[i2], hv[i2], lv[i2]);
            const size_t off = (size_t)(gg0 + gw) * 1280 + cb * 256 + ow;
            *(uint4*)&g_ahi[off]     = *(const uint4*)&hv[0];
            *(uint4*)&g_ahi[off + 8] = *(const uint4*)&hv[8];
            *(uint4*)&g_alo[off]     = *(const uint4*)&lv[0];
            *(uint4*)&g_alo[off + 8] = *(const uint4*)&lv[8];
        }
        __syncthreads();
    }
}

// ---------------- kernel 6: conv GEMM via mma.sync (proven) ----------------
#define CV_AS    72
#define CV_ATILE (64 * CV_AS)
#define CV_BUF   (CV_ATILE + 128 * CV_AS)
#define CV_SMEM_BYTES (2 * CV_BUF * 2)

__global__ __launch_bounds__(128) void conv_mma_kernel() {
    extern __shared__ __nv_bfloat16 smb[];
    const int tid = threadIdx.x;
    const int w = tid >> 5, lane = tid & 31;
    const int gm0 = blockIdx.x * 64;
    const int s = blockIdx.y;
    const int p = s >> 1;
    const int koff0 = (s & 1) * 640;

    const __nv_bfloat16* Asrc = (p == 2) ? g_alo : g_ahi;
    const __nv_bfloat16* Bsrc = (p == 1) ? g_wlo : g_whi;

    const int wm = (w & 1) * 32;
    const int wn = (w >> 1) * 64;

    float acc[2][8][4];
#pragma unroll
    for (int mt = 0; mt < 2; mt++)
#pragma unroll
        for (int nt = 0; nt < 8; nt++)
#pragma unroll
            for (int q = 0; q < 4; q++) acc[mt][nt][q] = 0.f;

    const uint32_t sbase = smem_u32(smb);
    int a_row[4], a_c8[4], b_row[8], b_c8[8];
#pragma unroll
    for (int q = 0; q < 4; q++) {
        const int i2 = tid + q * 128;
        a_row[q] = i2 >> 3; a_c8[q] = (i2 & 7) * 8;
    }
#pragma unroll
    for (int q = 0; q < 8; q++) {
        const int i2 = tid + q * 128;
        b_row[q] = i2 >> 3; b_c8[q] = (i2 & 7) * 8;
    }

#define CV_STAGE(cidx, buf) do {                                               \
    const int _ko = koff0 + (cidx) * 64;                                       \
    const uint32_t _sb = sbase + (buf) * (CV_BUF * 2);                         \
    _Pragma("unroll")                                                          \
    for (int q = 0; q < 4; q++)                                                \
        cpa16(_sb + (a_row[q] * CV_AS + a_c8[q]) * 2,                          \
              &Asrc[(size_t)(gm0 + a_row[q]) * 1280 + _ko + a_c8[q]]);         \
    _Pragma("unroll")                                                          \
    for (int q = 0; q < 8; q++)                                                \
        cpa16(_sb + (CV_ATILE + b_row[q] * CV_AS + b_c8[q]) * 2,               \
              &Bsrc[(size_t)b_row[q] * 1280 + _ko + b_c8[q]]);                 \
    asm volatile("cp.async.commit_group;");                                    \
} while (0)

    CV_STAGE(0, 0);

#pragma unroll 1
    for (int c = 0; c < 10; ++c) {
        if (c < 9) CV_STAGE(c + 1, (c + 1) & 1);
        if (c < 9) asm volatile("cp.async.wait_group 1;");
        else       asm volatile("cp.async.wait_group 0;");
        __syncthreads();

        const __nv_bfloat16* sA = smb + (c & 1) * CV_BUF;
        const __nv_bfloat16* sB = sA + CV_ATILE;

#pragma unroll
        for (int kb = 0; kb < 64; kb += 16) {
            unsigned bfr[8][2];
#pragma unroll
            for (int nt = 0; nt < 8; nt++) {
                const int base = (wn + nt * 8 + (lane >> 2)) * CV_AS + kb + (lane & 3) * 2;
                bfr[nt][0] = *(const unsigned*)&sB[base];
                bfr[nt][1] = *(const unsigned*)&sB[base + 8];
            }
            unsigned afr[2][4];
#pragma unroll
            for (int mt = 0; mt < 2; mt++) {
                const int base = (wm + mt * 16 + (lane >> 2)) * CV_AS + kb + (lane & 3) * 2;
                afr[mt][0] = *(const unsigned*)&sA[base];
                afr[mt][1] = *(const unsigned*)&sA[base + 8 * CV_AS];
                afr[mt][2] = *(const unsigned*)&sA[base + 8];
                afr[mt][3] = *(const unsigned*)&sA[base + 8 * CV_AS + 8];
            }
#pragma unroll
            for (int mt = 0; mt < 2; mt++)
#pragma unroll
                for (int nt = 0; nt < 8; nt++)
                    mma16816(acc[mt][nt], afr[mt], bfr[nt]);
        }
        __syncthreads();
    }

    float* dst = &g_part[s][0];
#pragma unroll
    for (int mt = 0; mt < 2; mt++) {
        const int m0 = gm0 + wm + mt * 16 + (lane >> 2);
#pragma unroll
        for (int nt = 0; nt < 8; nt++) {
            const int n0 = wn + nt * 8 + (lane & 3) * 2;
            *(float2*)&dst[(size_t)m0 * 128 + n0] = make_float2(acc[mt][nt][0], acc[mt][nt][1]);
            *(float2*)&dst[(size_t)(m0 + 8) * 128 + n0] = make_float2(acc[mt][nt][2], acc[mt][nt][3]);
        }
    }
}

// ---------------- kernel 7: reduce 6 partials + bias ----------------
__global__ void reduce_kernel(const float* __restrict__ conv_b,
                              float* __restrict__ out_main) {
    int t = blockIdx.x * 256 + threadIdx.x;
    int o4 = (t & 31) * 4;
    float4 s = *(const float4*)&g_part[0][(size_t)t * 4];
#pragma unroll
    for (int z = 1; z < 6; ++z) {
        const float4 p = *(const float4*)&g_part[z][(size_t)t * 4];
        s.x += p.x; s.y += p.y; s.z += p.z; s.w += p.w;
    }
    const float4 cb = __ldg((const float4*)&conv_b[o4]);
    s.x += cb.x; s.y += cb.y; s.z += cb.z; s.w += cb.w;
    *(float4*)&out_main[(size_t)t * 4] = s;
}

// ---------------- launch ----------------
extern "C" void kernel_launch(void* const* d_in, const int* in_sizes, int n_in,
                              void* d_out, int out_size) {
    (void)in_sizes; (void)n_in; (void)out_size;
    const float* points   = (const float*)d_in[0];
    const float* features = (const float*)d_in[1];
    const float* lift_w   = (const float*)d_in[2];
    const float* lift_b   = (const float*)d_in[3];
    const float* bnl_g    = (const float*)d_in[4];
    const float* bnl_b    = (const float*)d_in[5];
    const float* t1_w     = (const float*)d_in[6];
    const float* t1_b     = (const float*)d_in[7];
    const float* bn1_g    = (const float*)d_in[8];
    const float* bn1_b    = (const float*)d_in[9];
    const float* t2_w     = (const float*)d_in[10];
    const float* t2_b     = (const float*)d_in[11];
    const float* bn2_g    = (const float*)d_in[12];
    const float* bn2_b    = (const float*)d_in[13];
    const float* t3_w     = (const float*)d_in[14];
    const float* t3_b     = (const float*)d_in[15];
    const float* bn3_g    = (const float*)d_in[16];
    const float* bn3_b    = (const float*)d_in[17];
    const float* conv_w   = (const float*)d_in[18];
    const float* conv_b   = (const float*)d_in[19];
    const int*   rep_idx  = (const int*)d_in[20];

    float* out      = (float*)d_out;
    float* out_rep  = out;
    float* out_main = out + BQ * RQ * 3;

    cudaFuncSetAttribute(gemm_tnet, cudaFuncAttributeMaxDynamicSharedMemorySize, GS_SMEM_BYTES);
    cudaFuncSetAttribute(tf_kernel, cudaFuncAttributeMaxDynamicSharedMemorySize, TF_SMEM_BYTES);
    cudaFuncSetAttribute(conv_mma_kernel, cudaFuncAttributeMaxDynamicSharedMemorySize, CV_SMEM_BYTES);

    prep_kernel<<<PREP_TOTAL / 256, 256>>>(points, t1_w, t2_w, t3_w, conv_w);
    knn_kernel<<<dim3(128, 2), 512>>>(rep_idx);
    gatherpf_kernel<<<256, 256>>>(points, rep_idx, out_rep);
    gemm_tnet<<<dim3(64, 2), 128, GS_SMEM_BYTES>>>(0, t1_b, bn1_g, bn1_b, 64, 3, 0, 1);
    gemm_tnet<<<dim3(64, 2), 128, GS_SMEM_BYTES>>>(1, t2_b, bn2_g, bn2_b, 256, 12, 2, 1);
    gemm_tnet<<<dim3(64, 2), 128, GS_SMEM_BYTES>>>(2, t3_b, bn3_g, bn3_b, 256, 12, 2, 0);
    tf_kernel<<<256, 256, TF_SMEM_BYTES>>>(
        points, features, lift_w, lift_b, bnl_g, bnl_b, rep_idx);
    conv_mma_kernel<<<dim3(64, 6), 128, CV_SMEM_BYTES>>>();
    reduce_kernel<<<512, 256>>>(conv_b, out_main);
}

// round 15
// speedup vs baseline: 1.5961x; 1.3036x over previous
#include <cuda_runtime.h>
#include <cuda_bf16.h>
#include <cstdint>
#include <cfloat>
#include <cstddef>

#define BQ 2
#define NQ 8192
#define RQ 2048
#define KQ 16
#define COUTQ 128
#define GQ (BQ * RQ)

typedef unsigned long long u64;

// ---- packed fp32x2 helpers (tf kernel) ----
__device__ __forceinline__ u64 pk2(float lo, float hi) {
    u64 r;
    asm("mov.b64 %0, {%1, %2};" : "=l"(r)
        : "r"(__float_as_uint(lo)), "r"(__float_as_uint(hi)));
    return r;
}
__device__ __forceinline__ void fma2(u64& d, u64 a, u64 b) {
    asm("fma.rn.f32x2 %0, %1, %2, %0;" : "+l"(d) : "l"(a), "l"(b));
}
__device__ __forceinline__ float2 up2(u64 v) {
    unsigned lo, hi;
    asm("mov.b64 {%0, %1}, %2;" : "=r"(lo), "=r"(hi) : "l"(v));
    return make_float2(__uint_as_float(lo), __uint_as_float(hi));
}

// ---- mma.sync + cp.async helpers ----
__device__ __forceinline__ void mma16816(float* c, const unsigned* a, const unsigned* b) {
    asm volatile(
        "mma.sync.aligned.m16n8k16.row.col.f32.bf16.bf16.f32 "
        "{%0,%1,%2,%3}, {%4,%5,%6,%7}, {%8,%9}, {%0,%1,%2,%3};"
        : "+f"(c[0]), "+f"(c[1]), "+f"(c[2]), "+f"(c[3])
        : "r"(a[0]), "r"(a[1]), "r"(a[2]), "r"(a[3]), "r"(b[0]), "r"(b[1]));
}
__device__ __forceinline__ uint32_t smem_u32(const void* p) {
    uint32_t a;
    asm("{ .reg .u64 t; cvta.to.shared.u64 t, %1; cvt.u32.u64 %0, t; }"
        : "=r"(a) : "l"(p));
    return a;
}
__device__ __forceinline__ void cpa16(uint32_t s, const void* g) {
    asm volatile("cp.async.cg.shared.global [%0], [%1], 16;" :: "r"(s), "l"(g));
}
__device__ __forceinline__ void bf16split(float v, __nv_bfloat16& h, __nv_bfloat16& l) {
    h = __float2bfloat16(v);
    l = __float2bfloat16(v - __bfloat162float(h));
}

// ---------------- scratch (no allocations allowed) ----------------
__device__ int    g_nn[BQ * RQ * KQ];
__device__ float4 g_pts4[BQ * NQ];
__device__ __nv_bfloat16 g_pf_hi[GQ * 64],  g_pf_lo[GQ * 64];    // PF, K padded 48->64
__device__ __nv_bfloat16 g_w1hi[256 * 64],  g_w1lo[256 * 64];    // t1_w padded
__device__ __nv_bfloat16 g_w2hi[256 * 256], g_w2lo[256 * 256];
__device__ __nv_bfloat16 g_w3hi[256 * 256], g_w3lo[256 * 256];
__device__ __nv_bfloat16 g_h1hi[(size_t)GQ * 256], g_h1lo[(size_t)GQ * 256];
__device__ __nv_bfloat16 g_h2hi[(size_t)GQ * 256], g_h2lo[(size_t)GQ * 256];
__device__ float  g_T[(size_t)GQ * 256];
__device__ __nv_bfloat16 g_ahi[(size_t)GQ * 1280], g_alo[(size_t)GQ * 1280];
__device__ __nv_bfloat16 g_whi[COUTQ * 1280], g_wlo[COUTQ * 1280];
__device__ float  g_part[6][(size_t)GQ * COUTQ];

// ---------------- kernel 1: prep ----------------
#define PREP_TOTAL 327680

__global__ void prep_kernel(const float* __restrict__ points,
                            const float* __restrict__ t1_w,
                            const float* __restrict__ t2_w,
                            const float* __restrict__ t3_w,
                            const float* __restrict__ conv_w) {
    int e = blockIdx.x * 256 + threadIdx.x;
    if (e < 163840) {
        bf16split(__ldg(&conv_w[e]), g_whi[e], g_wlo[e]);
    } else if (e < 180224) {
        int p = e - 163840;
        const float* pp = points + (size_t)p * 3;
        float x = __ldg(pp), y = __ldg(pp + 1), z = __ldg(pp + 2);
        g_pts4[p] = make_float4(x, y, z, fmaf(z, z, fmaf(y, y, x * x)));
    } else if (e < 196608) {
        int p = e - 180224;
        int n = p >> 6, j = p & 63;
        float v = (j < 48) ? __ldg(&t1_w[n * 48 + j]) : 0.f;
        bf16split(v, g_w1hi[p], g_w1lo[p]);
    } else if (e < 262144) {
        int p = e - 196608;
        bf16split(__ldg(&t2_w[p]), g_w2hi[p], g_w2lo[p]);
    } else if (e < PREP_TOTAL) {
        int p = e - 262144;
        bf16split(__ldg(&t3_w[p]), g_w3hi[p], g_w3lo[p]);
    }
}

// ---------------- kernel 2: kNN — shared-staged points + float-tau filter ----------------
// grid (64, 2), 1024 threads = 32 warps; warp w owns rep blockIdx.x*32 + w.
// Points staged once to shared (kills the 512MB L2 re-read of g_pts4).
__device__ __forceinline__ u64 knn_pad(int s) {
    return 0xFFFFFFFF00000000ull | (unsigned)(0x40000000 + s);
}

__device__ __forceinline__ void knn_flush(u64* S, int lane) {
    __syncwarp();
    u64 k0 = S[lane], k1 = S[lane + 32];
    int r0 = 0, r1 = 0;
#pragma unroll
    for (int j = 0; j < 64; ++j) {
        u64 kj = S[j];
        r0 += (kj < k0); r1 += (kj < k1);
    }
    __syncwarp();
    S[r0] = k0; S[r1] = k1;       // ranks form a permutation (keys unique)
    __syncwarp();
    S[17 + lane] = knn_pad(17 + lane);
    if (lane < 15) S[49 + lane] = knn_pad(49 + lane);
    __syncwarp();
}

#define KNN_SMEM_BYTES (NQ * 16 + 32 * 64 * 8)

__global__ __launch_bounds__(1024, 1) void knn_kernel(const int* __restrict__ rep_idx) {
    extern __shared__ float4 sk[];              // [8192] (x,y,z,sq)
    u64* slots = (u64*)(sk + NQ);               // [32][64]
    const int tid = threadIdx.x;
    const int w = tid >> 5, lane = tid & 31;
    const int b = blockIdx.y;

    const float4* P = g_pts4 + (size_t)b * NQ;
#pragma unroll
    for (int q = 0; q < 8; ++q) sk[tid + q * 1024] = __ldg(&P[tid + q * 1024]);

    u64* S = slots + w * 64;
    S[lane] = knn_pad(lane);
    S[lane + 32] = knn_pad(lane + 32);
    __syncthreads();

    const int r = blockIdx.x * 32 + w;
    const int rpt = __ldg(&rep_idx[r]);
    const float4 rp = sk[rpt];

    int cnt = 17;
    float tauf = FLT_MAX;

#pragma unroll 1
    for (int it = 0; it < 256; ++it) {
        const int c = (it << 5) + lane;
        const float4 q = sk[c];
        const float dot = fmaf(rp.z, q.z, fmaf(rp.y, q.y, rp.x * q.x));
        const float d2  = fmaf(-2.f, dot, rp.w + q.w);
        const bool pred = d2 <= tauf;                       // superset of exact predicate
        const unsigned bal = __ballot_sync(0xffffffffu, pred);
        if (bal) {                                          // warp-uniform skip
            const int n = __popc(bal);
            if (cnt + n > 64) {
                knn_flush(S, lane);
                cnt = 17;
                const unsigned u = (unsigned)(S[16] >> 32); // real key post-flush
                const unsigned sb = (u & 0x80000000u) ? (u & 0x7FFFFFFFu) : ~u;
                tauf = __uint_as_float(sb);
            }
            if (pred) {
                const unsigned sb2 = __float_as_uint(d2);
                const unsigned uu = (sb2 & 0x80000000u) ? ~sb2 : (sb2 | 0x80000000u);
                S[cnt + __popc(bal & ((1u << lane) - 1u))] =
                    ((u64)uu << 32) | (unsigned)c;
            }
            cnt += n;
        }
    }
    if (cnt > 17) knn_flush(S, lane);

    if (lane < 16)
        g_nn[((size_t)b * RQ + r) * KQ + lane] =
            (int)(unsigned)(S[lane + 1] & 0xFFFFFFFFull);
}

// ---------------- kernel 3: gather PF (padded K=64) + rep_pos ----------------
__global__ __launch_bounds__(256) void gatherpf_kernel(
    const float* __restrict__ points, const int* __restrict__ rep_idx,
    float* __restrict__ out_rep)
{
    const int tid = threadIdx.x;
    const int g = tid >> 4, k = tid & 15;
    const int gg = blockIdx.x * 16 + g;
    const int b = gg >> 11, rl = gg & 2047;
    const int rpt = __ldg(&rep_idx[rl]);
    const float* rpp = points + ((size_t)b * NQ + rpt) * 3;
    const float rx = __ldg(rpp), ry = __ldg(rpp + 1), rz = __ldg(rpp + 2);
    const int nb = g_nn[gg * KQ + k];
    const float* npp = points + ((size_t)b * NQ + nb) * 3;
    const float pv[3] = { __ldg(npp) - rx, __ldg(npp + 1) - ry, __ldg(npp + 2) - rz };
#pragma unroll
    for (int i = 0; i < 3; i++) {
        __nv_bfloat16 h, l;
        bf16split(pv[i], h, l);
        g_pf_hi[gg * 64 + k * 3 + i] = h;
        g_pf_lo[gg * 64 + k * 3 + i] = l;
    }
    if (k < 8) {   // zero pad j in [48,64)
        const __nv_bfloat16 z = __float2bfloat16(0.f);
        g_pf_hi[gg * 64 + 48 + k * 2 + 0] = z;
        g_pf_hi[gg * 64 + 48 + k * 2 + 1] = z;
        g_pf_lo[gg * 64 + 48 + k * 2 + 0] = z;
        g_pf_lo[gg * 64 + 48 + k * 2 + 1] = z;
    }
    if (k == 0) {
        out_rep[gg * 3 + 0] = rx; out_rep[gg * 3 + 1] = ry; out_rep[gg * 3 + 2] = rz;
    }
}

// ---------------- kernel 4: T-net GEMM (device-side operand selection) ----------------
#define GS_AS    72
#define GS_ATILE (64 * GS_AS)
#define GS_BUF   (GS_ATILE + 128 * GS_AS)
#define GS_SMEM_BYTES (2 * GS_BUF * 2)

__global__ __launch_bounds__(128) void gemm_tnet(
    int stage,
    const float* __restrict__ bias, const float* __restrict__ bng,
    const float* __restrict__ bnb,
    int KD, int niter, int cl2, int relu)
{
    const __nv_bfloat16 *Ahi, *Alo, *Bhi, *Blo;
    __nv_bfloat16 *Ohi = nullptr, *Olo = nullptr;
    float* Of32 = nullptr;
    if (stage == 0) {
        Ahi = g_pf_hi; Alo = g_pf_lo; Bhi = g_w1hi; Blo = g_w1lo;
        Ohi = g_h1hi;  Olo = g_h1lo;
    } else if (stage == 1) {
        Ahi = g_h1hi;  Alo = g_h1lo;  Bhi = g_w2hi; Blo = g_w2lo;
        Ohi = g_h2hi;  Olo = g_h2lo;
    } else {
        Ahi = g_h2hi;  Alo = g_h2lo;  Bhi = g_w3hi; Blo = g_w3lo;
        Of32 = g_T;
    }

    extern __shared__ __nv_bfloat16 smb[];
    const int tid = threadIdx.x;
    const int w = tid >> 5, lane = tid & 31;
    const int gm0 = blockIdx.x * 64;
    const int gn0 = blockIdx.y * 128;
    const int wm = (w & 1) * 32;
    const int wn = (w >> 1) * 64;

    float acc[2][8][4];
#pragma unroll
    for (int mt = 0; mt < 2; mt++)
#pragma unroll
        for (int nt = 0; nt < 8; nt++)
#pragma unroll
            for (int q = 0; q < 4; q++) acc[mt][nt][q] = 0.f;

    const uint32_t sbase = smem_u32(smb);

#define TN_STAGE(cidx, buf) do {                                               \
    const int _p = (cidx) >> cl2;                                              \
    const int _ko = ((cidx) & ((1 << cl2) - 1)) << 6;                          \
    const __nv_bfloat16* _As = (_p == 2) ? Alo : Ahi;                          \
    const __nv_bfloat16* _Bs = (_p == 1) ? Blo : Bhi;                          \
    const uint32_t _sb = sbase + (buf) * (GS_BUF * 2);                         \
    _Pragma("unroll")                                                          \
    for (int q = 0; q < 4; q++) {                                              \
        const int i2 = tid + q * 128;                                          \
        const int row = i2 >> 3, c8 = (i2 & 7) * 8;                            \
        cpa16(_sb + (row * GS_AS + c8) * 2,                                    \
              &_As[(size_t)(gm0 + row) * KD + _ko + c8]);                      \
    }                                                                          \
    _Pragma("unroll")                                                          \
    for (int q = 0; q < 8; q++) {                                              \
        const int i2 = tid + q * 128;                                          \
        const int row = i2 >> 3, c8 = (i2 & 7) * 8;                            \
        cpa16(_sb + (GS_ATILE + row * GS_AS + c8) * 2,                         \
              &_Bs[(size_t)(gn0 + row) * KD + _ko + c8]);                      \
    }                                                                          \
    asm volatile("cp.async.commit_group;");                                    \
} while (0)

    TN_STAGE(0, 0);

#pragma unroll 1
    for (int c = 0; c < niter; ++c) {
        if (c < niter - 1) {
            TN_STAGE(c + 1, (c + 1) & 1);
            asm volatile("cp.async.wait_group 1;");
        } else {
            asm volatile("cp.async.wait_group 0;");
        }
        __syncthreads();

        const __nv_bfloat16* sA = smb + (c & 1) * GS_BUF;
        const __nv_bfloat16* sB = sA + GS_ATILE;

#pragma unroll
        for (int kb = 0; kb < 64; kb += 16) {
            unsigned bfr[8][2];
#pragma unroll
            for (int nt = 0; nt < 8; nt++) {
                const int base = (wn + nt * 8 + (lane >> 2)) * GS_AS + kb + (lane & 3) * 2;
                bfr[nt][0] = *(const unsigned*)&sB[base];
                bfr[nt][1] = *(const unsigned*)&sB[base + 8];
            }
            unsigned afr[2][4];
#pragma unroll
            for (int mt = 0; mt < 2; mt++) {
                const int base = (wm + mt * 16 + (lane >> 2)) * GS_AS + kb + (lane & 3) * 2;
                afr[mt][0] = *(const unsigned*)&sA[base];
                afr[mt][1] = *(const unsigned*)&sA[base + 8 * GS_AS];
                afr[mt][2] = *(const unsigned*)&sA[base + 8];
                afr[mt][3] = *(const unsigned*)&sA[base + 8 * GS_AS + 8];
            }
#pragma unroll
            for (int mt = 0; mt < 2; mt++)
#pragma unroll
                for (int nt = 0; nt < 8; nt++)
                    mma16816(acc[mt][nt], afr[mt], bfr[nt]);
        }
        __syncthreads();
    }

    const bool f32mode = (stage == 2);
#pragma unroll
    for (int mt = 0; mt < 2; mt++) {
        const int m0 = gm0 + wm + mt * 16 + (lane >> 2);
#pragma unroll
        for (int nt = 0; nt < 8; nt++) {
            const int n0 = gn0 + wn + nt * 8 + (lane & 3) * 2;
            const float2 bs = *(const float2*)&bias[n0];
            const float2 gv = *(const float2*)&bng[n0];
            const float2 bv = *(const float2*)&bnb[n0];
            float v00 = fmaf(acc[mt][nt][0] + bs.x, gv.x, bv.x);
            float v01 = fmaf(acc[mt][nt][1] + bs.y, gv.y, bv.y);
            float v10 = fmaf(acc[mt][nt][2] + bs.x, gv.x, bv.x);
            float v11 = fmaf(acc[mt][nt][3] + bs.y, gv.y, bv.y);
            if (relu) {
                v00 = fmaxf(v00, 0.f); v01 = fmaxf(v01, 0.f);
                v10 = fmaxf(v10, 0.f); v11 = fmaxf(v11, 0.f);
            }
            if (f32mode) {
                *(float2*)&Of32[(size_t)m0 * 256 + n0] = make_float2(v00, v01);
                *(float2*)&Of32[(size_t)(m0 + 8) * 256 + n0] = make_float2(v10, v11);
            } else {
                __nv_bfloat16 h0, l0, h1, l1;
                bf16split(v00, h0, l0); bf16split(v01, h1, l1);
                *(__nv_bfloat162*)&Ohi[(size_t)m0 * 256 + n0] = __halves2bfloat162(h0, h1);
                *(__nv_bfloat162*)&Olo[(size_t)m0 * 256 + n0] = __halves2bfloat162(l0, l1);
                bf16split(v10, h0, l0); bf16split(v11, h1, l1);
                *(__nv_bfloat162*)&Ohi[(size_t)(m0 + 8) * 256 + n0] = __halves2bfloat162(h0, h1);
                *(__nv_bfloat162*)&Olo[(size_t)(m0 + 8) * 256 + n0] = __halves2bfloat162(l0, l1);
            }
        }
    }
}

// ---------------- kernel 5: gather feat + lift + Tf -> bf16 hi/lo ----------------
#define TF_SMEM_FLOATS (4096 + 16 * 1288)
#define TF_SMEM_BYTES  (TF_SMEM_FLOATS * 4)
#define SF_OFF 4096

__global__ __launch_bounds__(256, 2) void tf_kernel(
    const float* __restrict__ points,  const float* __restrict__ features,
    const float* __restrict__ lift_w,  const float* __restrict__ lift_b,
    const float* __restrict__ bnl_g,   const float* __restrict__ bnl_b,
    const int* __restrict__ rep_idx)
{
    extern __shared__ float sm[];
    float* sH = sm;
    float* sF = sm + SF_OFF;
    const int tid = threadIdx.x;
    const int gg0 = blockIdx.x * 16;

    {
        const int g = tid >> 4, k = tid & 15;
        const int gg = gg0 + g;
        const int b = gg >> 11, rl = gg & 2047;
        const int rpt = __ldg(&rep_idx[rl]);
        const float* rpp = points + ((size_t)b * NQ + rpt) * 3;
        const float rx = __ldg(rpp), ry = __ldg(rpp + 1), rz = __ldg(rpp + 2);
        const int nb = g_nn[gg * KQ + k];
        const float* npp = points + ((size_t)b * NQ + nb) * 3;
        const float px = __ldg(npp) - rx, py = __ldg(npp + 1) - ry, pz = __ldg(npp + 2) - rz;
        float* fl = &sF[g * 1288 + k * 80];
#pragma unroll
        for (int j = 0; j < 16; j++) {
            float d = fmaf(pz, __ldg(&lift_w[j * 3 + 2]),
                      fmaf(py, __ldg(&lift_w[j * 3 + 1]), px * __ldg(&lift_w[j * 3 + 0])));
            float v = fmaf(d + __ldg(&lift_b[j]), __ldg(&bnl_g[j]), __ldg(&bnl_b[j]));
            fl[j] = fmaxf(v, 0.f);
        }
        const float4* fr = (const float4*)(features + ((size_t)b * NQ + nb) * 64);
        float4* fd = (float4*)(fl + 16);
#pragma unroll
        for (int q = 0; q < 16; q++) fd[q] = __ldg(fr + q);
    }
    __syncthreads();

    const int aT = tid & 15, gT = tid >> 4;
    u64 trp[16];
#pragma unroll
    for (int q = 0; q < 4; q++) {
        const float4 v = __ldg((const float4*)&g_T[(size_t)(gg0 + gT) * 256 + aT * 16 + q * 4]);
        trp[q * 4 + 0] = pk2(v.x, v.x); trp[q * 4 + 1] = pk2(v.y, v.y);
        trp[q * 4 + 2] = pk2(v.z, v.z); trp[q * 4 + 3] = pk2(v.w, v.w);
    }

    const int gw = tid >> 4;
    const int ow = (tid & 15) * 16;
#pragma unroll 1
    for (int cb = 0; cb < 5; ++cb) {
#pragma unroll
        for (int q = 0; q < 4; q++) {
            const int c0 = cb * 16 + q * 4;
            u64 s01 = 0ull, s23 = 0ull;
#pragma unroll
            for (int k = 0; k < 16; k++) {
                const ulonglong2 f = *(const ulonglong2*)&sF[gT * 1288 + k * 80 + c0];
                fma2(s01, trp[k], f.x);
                fma2(s23, trp[k], f.y);
            }
            const float2 v01 = up2(s01), v23 = up2(s23);
            sH[gT * 256 + (q * 4 + 0) * 16 + aT] = v01.x;
            sH[gT * 256 + (q * 4 + 1) * 16 + aT] = v01.y;
            sH[gT * 256 + (q * 4 + 2) * 16 + aT] = v23.x;
            sH[gT * 256 + (q * 4 + 3) * 16 + aT] = v23.y;
        }
        __syncthreads();
        {
            const float* src = &sH[gw * 256 + ow];
            __align__(16) __nv_bfloat16 hv[16], lv[16];
#pragma unroll
            for (int i2 = 0; i2 < 16; i2++) bf16split(src[i2], hv[i2], lv[i2]);
            const size_t off = (size_t)(gg0 + gw) * 1280 + cb * 256 + ow;
            *(uint4*)&g_ahi[off]     = *(const uint4*)&hv[0];
            *(uint4*)&g_ahi[off + 8] = *(const uint4*)&hv[8];
            *(uint4*)&g_alo[off]     = *(const uint4*)&lv[0];
            *(uint4*)&g_alo[off + 8] = *(const uint4*)&lv[8];
        }
        __syncthreads();
    }
}

// ---------------- kernel 6: conv GEMM via mma.sync (proven) ----------------
#define CV_AS    72
#define CV_ATILE (64 * CV_AS)
#define CV_BUF   (CV_ATILE + 128 * CV_AS)
#define CV_SMEM_BYTES (2 * CV_BUF * 2)

__global__ __launch_bounds__(128) void conv_mma_kernel() {
    extern __shared__ __nv_bfloat16 smb[];
    const int tid = threadIdx.x;
    const int w = tid >> 5, lane = tid & 31;
    const int gm0 = blockIdx.x * 64;
    const int s = blockIdx.y;
    const int p = s >> 1;
    const int koff0 = (s & 1) * 640;

    const __nv_bfloat16* Asrc = (p == 2) ? g_alo : g_ahi;
    const __nv_bfloat16* Bsrc = (p == 1) ? g_wlo : g_whi;

    const int wm = (w & 1) * 32;
    const int wn = (w >> 1) * 64;

    float acc[2][8][4];
#pragma unroll
    for (int mt = 0; mt < 2; mt++)
#pragma unroll
        for (int nt = 0; nt < 8; nt++)
#pragma unroll
            for (int q = 0; q < 4; q++) acc[mt][nt][q] = 0.f;

    const uint32_t sbase = smem_u32(smb);
    int a_row[4], a_c8[4], b_row[8], b_c8[8];
#pragma unroll
    for (int q = 0; q < 4; q++) {
        const int i2 = tid + q * 128;
        a_row[q] = i2 >> 3; a_c8[q] = (i2 & 7) * 8;
    }
#pragma unroll
    for (int q = 0; q < 8; q++) {
        const int i2 = tid + q * 128;
        b_row[q] = i2 >> 3; b_c8[q] = (i2 & 7) * 8;
    }

#define CV_STAGE(cidx, buf) do {                                               \
    const int _ko = koff0 + (cidx) * 64;                                       \
    const uint32_t _sb = sbase + (buf) * (CV_BUF * 2);                         \
    _Pragma("unroll")                                                          \
    for (int q = 0; q < 4; q++)                                                \
        cpa16(_sb + (a_row[q] * CV_AS + a_c8[q]) * 2,                          \
              &Asrc[(size_t)(gm0 + a_row[q]) * 1280 + _ko + a_c8[q]]);         \
    _Pragma("unroll")                                                          \
    for (int q = 0; q < 8; q++)                                                \
        cpa16(_sb + (CV_ATILE + b_row[q] * CV_AS + b_c8[q]) * 2,               \
              &Bsrc[(size_t)b_row[q] * 1280 + _ko + b_c8[q]]);                 \
    asm volatile("cp.async.commit_group;");                                    \
} while (0)

    CV_STAGE(0, 0);

#pragma unroll 1
    for (int c = 0; c < 10; ++c) {
        if (c < 9) CV_STAGE(c + 1, (c + 1) & 1);
        if (c < 9) asm volatile("cp.async.wait_group 1;");
        else       asm volatile("cp.async.wait_group 0;");
        __syncthreads();

        const __nv_bfloat16* sA = smb + (c & 1) * CV_BUF;
        const __nv_bfloat16* sB = sA + CV_ATILE;

#pragma unroll
        for (int kb = 0; kb < 64; kb += 16) {
            unsigned bfr[8][2];
#pragma unroll
            for (int nt = 0; nt < 8; nt++) {
                const int base = (wn + nt * 8 + (lane >> 2)) * CV_AS + kb + (lane & 3) * 2;
                bfr[nt][0] = *(const unsigned*)&sB[base];
                bfr[nt][1] = *(const unsigned*)&sB[base + 8];
            }
            unsigned afr[2][4];
#pragma unroll
            for (int mt = 0; mt < 2; mt++) {
                const int base = (wm + mt * 16 + (lane >> 2)) * CV_AS + kb + (lane & 3) * 2;
                afr[mt][0] = *(const unsigned*)&sA[base];
                afr[mt][1] = *(const unsigned*)&sA[base + 8 * CV_AS];
                afr[mt][2] = *(const unsigned*)&sA[base + 8];
                afr[mt][3] = *(const unsigned*)&sA[base + 8 * CV_AS + 8];
            }
#pragma unroll
            for (int mt = 0; mt < 2; mt++)
#pragma unroll
                for (int nt = 0; nt < 8; nt++)
                    mma16816(acc[mt][nt], afr[mt], bfr[nt]);
        }
        __syncthreads();
    }

    float* dst = &g_part[s][0];
#pragma unroll
    for (int mt = 0; mt < 2; mt++) {
        const int m0 = gm0 + wm + mt * 16 + (lane >> 2);
#pragma unroll
        for (int nt = 0; nt < 8; nt++) {
            const int n0 = wn + nt * 8 + (lane & 3) * 2;
            *(float2*)&dst[(size_t)m0 * 128 + n0] = make_float2(acc[mt][nt][0], acc[mt][nt][1]);
            *(float2*)&dst[(size_t)(m0 + 8) * 128 + n0] = make_float2(acc[mt][nt][2], acc[mt][nt][3]);
        }
    }
}

// ---------------- kernel 7: reduce 6 partials + bias ----------------
__global__ void reduce_kernel(const float* __restrict__ conv_b,
                              float* __restrict__ out_main) {
    int t = blockIdx.x * 256 + threadIdx.x;
    int o4 = (t & 31) * 4;
    float4 s = *(const float4*)&g_part[0][(size_t)t * 4];
#pragma unroll
    for (int z = 1; z < 6; ++z) {
        const float4 p = *(const float4*)&g_part[z][(size_t)t * 4];
        s.x += p.x; s.y += p.y; s.z += p.z; s.w += p.w;
    }
    const float4 cb = __ldg((const float4*)&conv_b[o4]);
    s.x += cb.x; s.y += cb.y; s.z += cb.z; s.w += cb.w;
    *(float4*)&out_main[(size_t)t * 4] = s;
}

// ---------------- launch ----------------
extern "C" void kernel_launch(void* const* d_in, const int* in_sizes, int n_in,
                              void* d_out, int out_size) {
    (void)in_sizes; (void)n_in; (void)out_size;
    const float* points   = (const float*)d_in[0];
    const float* features = (const float*)d_in[1];
    const float* lift_w   = (const float*)d_in[2];
    const float* lift_b   = (const float*)d_in[3];
    const float* bnl_g    = (const float*)d_in[4];
    const float* bnl_b    = (const float*)d_in[5];
    const float* t1_w     = (const float*)d_in[6];
    const float* t1_b     = (const float*)d_in[7];
    const float* bn1_g    = (const float*)d_in[8];
    const float* bn1_b    = (const float*)d_in[9];
    const float* t2_w     = (const float*)d_in[10];
    const float* t2_b     = (const float*)d_in[11];
    const float* bn2_g    = (const float*)d_in[12];
    const float* bn2_b    = (const float*)d_in[13];
    const float* t3_w     = (const float*)d_in[14];
    const float* t3_b     = (const float*)d_in[15];
    const float* bn3_g    = (const float*)d_in[16];
    const float* bn3_b    = (const float*)d_in[17];
    const float* conv_w   = (const float*)d_in[18];
    const float* conv_b   = (const float*)d_in[19];
    const int*   rep_idx  = (const int*)d_in[20];

    float* out      = (float*)d_out;
    float* out_rep  = out;
    float* out_main = out + BQ * RQ * 3;

    cudaFuncSetAttribute(knn_kernel, cudaFuncAttributeMaxDynamicSharedMemorySize, KNN_SMEM_BYTES);
    cudaFuncSetAttribute(gemm_tnet, cudaFuncAttributeMaxDynamicSharedMemorySize, GS_SMEM_BYTES);
    cudaFuncSetAttribute(tf_kernel, cudaFuncAttributeMaxDynamicSharedMemorySize, TF_SMEM_BYTES);
    cudaFuncSetAttribute(conv_mma_kernel, cudaFuncAttributeMaxDynamicSharedMemorySize, CV_SMEM_BYTES);

    prep_kernel<<<PREP_TOTAL / 256, 256>>>(points, t1_w, t2_w, t3_w, conv_w);
    knn_kernel<<<dim3(64, 2), 1024, KNN_SMEM_BYTES>>>(rep_idx);
    gatherpf_kernel<<<256, 256>>>(points, rep_idx, out_rep);
    gemm_tnet<<<dim3(64, 2), 128, GS_SMEM_BYTES>>>(0, t1_b, bn1_g, bn1_b, 64, 3, 0, 1);
    gemm_tnet<<<dim3(64, 2), 128, GS_SMEM_BYTES>>>(1, t2_b, bn2_g, bn2_b, 256, 12, 2, 1);
    gemm_tnet<<<dim3(64, 2), 128, GS_SMEM_BYTES>>>(2, t3_b, bn3_g, bn3_b, 256, 12, 2, 0);
    tf_kernel<<<256, 256, TF_SMEM_BYTES>>>(
        points, features, lift_w, lift_b, bnl_g, bnl_b, rep_idx);
    conv_mma_kernel<<<dim3(64, 6), 128, CV_SMEM_BYTES>>>();
    reduce_kernel<<<512, 256>>>(conv_b, out_main);
}